// round 4
// baseline (speedup 1.0000x reference)
#include <cuda_runtime.h>
#include <cuda_bf16.h>
#include <cstdint>

#define B_  16
#define H_  8
#define L_  1024
#define DK_ 64
#define BH_ 128
#define NROWS_ (BH_ * L_)
#define SCALE_ 0.125f

// ---------------------------------------------------------------------------
// Device scratch
// ---------------------------------------------------------------------------
__device__ float g_l1[(size_t)BH_ * L_ * L_];
__device__ __nv_bfloat16 g_cath[(size_t)BH_ * L_ * 128];  // [bh][row][Q|K]
__device__ __nv_bfloat16 g_catl[(size_t)BH_ * L_ * 128];
__device__ __nv_bfloat16 g_Wh[(size_t)H_ * L_ * 128];     // pre-scaled by 0.125
__device__ __nv_bfloat16 g_Wl[(size_t)H_ * L_ * 128];
__device__ __nv_bfloat16 g_Vth[(size_t)BH_ * DK_ * L_];   // [bh][d][k]
__device__ __nv_bfloat16 g_Vtl[(size_t)BH_ * DK_ * L_];
__device__ float2 g_ts1[(size_t)NROWS_ * 16];             // per (row, 64-tile) (m, s)
__device__ float2 g_ts2[(size_t)NROWS_ * 16];
__device__ float2 g_stat1[NROWS_];                        // per row (M, 1/S)
__device__ float2 g_stat2[NROWS_];

// ---------------------------------------------------------------------------
// PTX helpers
// ---------------------------------------------------------------------------
__device__ __forceinline__ uint32_t smem_u32(const void* p) {
    uint32_t a;
    asm("{ .reg .u64 t; cvta.to.shared.u64 t, %1; cvt.u32.u64 %0, t; }" : "=r"(a) : "l"(p));
    return a;
}

__device__ __forceinline__ void mma_bf16(float (&c)[4], const uint32_t (&a)[4],
                                         const uint32_t b0, const uint32_t b1) {
    asm volatile(
        "mma.sync.aligned.m16n8k16.row.col.f32.bf16.bf16.f32 "
        "{%0,%1,%2,%3}, {%4,%5,%6,%7}, {%8,%9}, {%0,%1,%2,%3};\n"
        : "+f"(c[0]), "+f"(c[1]), "+f"(c[2]), "+f"(c[3])
        : "r"(a[0]), "r"(a[1]), "r"(a[2]), "r"(a[3]), "r"(b0), "r"(b1));
}

__device__ __forceinline__ void ldm_x4(uint32_t (&r)[4], uint32_t addr) {
    asm volatile("ldmatrix.sync.aligned.m8n8.x4.shared.b16 {%0,%1,%2,%3}, [%4];"
                 : "=r"(r[0]), "=r"(r[1]), "=r"(r[2]), "=r"(r[3]) : "r"(addr));
}

// A-frag (m16k16) address: lane -> row (lane&15), k-half (lane>>4)*8
__device__ __forceinline__ uint32_t a_addr(uint32_t base, int row0, int k0, int ST, int lane) {
    return base + (uint32_t)(((row0 + (lane & 15)) * ST + k0 + ((lane >> 4) << 3)) * 2);
}
// B-frag pair (two n8k16 groups) address: Bt[n][k] layout
__device__ __forceinline__ uint32_t b_addr(uint32_t base, int n0, int k0, int ST, int lane) {
    int nr = n0 + ((lane >> 4) << 3) + (lane & 7);
    int kc = k0 + (((lane >> 3) & 1) << 3);
    return base + (uint32_t)((nr * ST + kc) * 2);
}

__device__ __forceinline__ void split_pack4(const float* f, uint2& hp, uint2& lp) {
    unsigned short* hw = (unsigned short*)&hp;
    unsigned short* lw = (unsigned short*)&lp;
    #pragma unroll
    for (int k = 0; k < 4; k++) {
        __nv_bfloat16 hb = __float2bfloat16(f[k]);
        float r = f[k] - __bfloat162float(hb);
        hw[k] = __bfloat16_as_ushort(hb);
        lw[k] = __bfloat16_as_ushort(__float2bfloat16(r));
    }
}

// ---------------------------------------------------------------------------
// Prep kernels
// ---------------------------------------------------------------------------
__global__ void cat_kernel(const float* __restrict__ Q, const float* __restrict__ K) {
    int tid = blockIdx.x * blockDim.x + threadIdx.x;
    int q = tid & 31;
    size_t row = (size_t)(tid >> 5);
    const float* src = (q < 16) ? (Q + row * 64 + q * 4)
                                : (K + row * 64 + (q - 16) * 4);
    int col = (q < 16) ? q * 4 : 64 + (q - 16) * 4;
    float4 v = *(const float4*)src;
    float f[4] = {v.x, v.y, v.z, v.w};
    uint2 hp, lp;
    split_pack4(f, hp, lp);
    *(uint2*)(g_cath + row * 128 + col) = hp;
    *(uint2*)(g_catl + row * 128 + col) = lp;
}

__global__ void wsplit_kernel(const float* __restrict__ W) {
    int tid = blockIdx.x * blockDim.x + threadIdx.x;
    float4 v = ((const float4*)W)[tid];
    float f[4] = {v.x * SCALE_, v.y * SCALE_, v.z * SCALE_, v.w * SCALE_};
    uint2 hp, lp;
    split_pack4(f, hp, lp);
    *(uint2*)(g_Wh + (size_t)tid * 4) = hp;
    *(uint2*)(g_Wl + (size_t)tid * 4) = lp;
}

__global__ void vtrans_kernel(const float* __restrict__ V) {
    __shared__ float tile[64][65];
    int bh = blockIdx.y, k0 = blockIdx.x << 6, t = threadIdx.x;
    const float* src = V + ((size_t)bh * L_ + k0) * DK_;
    #pragma unroll
    for (int i = 0; i < 16; i++) {
        int lin = t + i * 256;
        int r = lin >> 6, d = lin & 63;
        tile[r][d] = src[r * DK_ + d];
    }
    __syncthreads();
    #pragma unroll
    for (int i = 0; i < 16; i++) {
        int lin = t + i * 256;
        int d = lin >> 6, c = lin & 63;
        float x = tile[c][d];
        __nv_bfloat16 hb = __float2bfloat16(x);
        float r = x - __bfloat162float(hb);
        size_t o = ((size_t)bh * DK_ + d) * L_ + k0 + c;
        g_Vth[o] = hb;
        g_Vtl[o] = __float2bfloat16(r);
    }
}

// ---------------------------------------------------------------------------
// Logits GEMM with ldmatrix + per-tile softmax stats.
// MODE 0: l1 = Q.K^T (K=64); MODE 1: l2 = W.cat^T (K=128)
// ---------------------------------------------------------------------------
template <int MODE>
__global__ void __launch_bounds__(256) mm_logits_kernel(float* __restrict__ l2out) {
    constexpr int KD = (MODE == 0) ? 64 : 128;
    constexpr int ST = KD + 8;
    extern __shared__ __align__(16) __nv_bfloat16 sm[];
    __nv_bfloat16* sAh = sm;
    __nv_bfloat16* sAl = sm + 128 * ST;
    __nv_bfloat16* sBh = sm + 2 * 128 * ST;
    __nv_bfloat16* sBl = sm + 3 * 128 * ST;

    const int t = threadIdx.x;
    const int bh = blockIdx.z, h = bh & (H_ - 1);
    const int q0 = blockIdx.x << 7;
    const int n0 = blockIdx.y << 7;

    const __nv_bfloat16 *Ah, *Al, *Bh, *Bl;
    if (MODE == 0) {
        size_t base = (size_t)bh * L_ * 128;
        Ah = g_cath + base + (size_t)q0 * 128;
        Al = g_catl + base + (size_t)q0 * 128;
        Bh = g_cath + base + (size_t)n0 * 128 + 64;
        Bl = g_catl + base + (size_t)n0 * 128 + 64;
    } else {
        Ah = g_Wh + ((size_t)h * L_ + q0) * 128;
        Al = g_Wl + ((size_t)h * L_ + q0) * 128;
        Bh = g_cath + ((size_t)bh * L_ + n0) * 128;
        Bl = g_catl + ((size_t)bh * L_ + n0) * 128;
    }

    constexpr int CPR = KD / 8;
    constexpr int ITERS = 128 * CPR / 256;
    #pragma unroll
    for (int i = 0; i < ITERS; i++) {
        int lin = t + i * 256;
        int row = lin / CPR, pc = lin % CPR;
        *(uint4*)(sAh + row * ST + pc * 8) = *(const uint4*)(Ah + (size_t)row * 128 + pc * 8);
        *(uint4*)(sAl + row * ST + pc * 8) = *(const uint4*)(Al + (size_t)row * 128 + pc * 8);
        *(uint4*)(sBh + row * ST + pc * 8) = *(const uint4*)(Bh + (size_t)row * 128 + pc * 8);
        *(uint4*)(sBl + row * ST + pc * 8) = *(const uint4*)(Bl + (size_t)row * 128 + pc * 8);
    }
    __syncthreads();

    const int w = t >> 5, lane = t & 31;
    const int wm = (w >> 1) << 5;          // 0,32,64,96
    const int wn = (w & 1) << 6;           // 0,64
    const int gid = lane >> 2, tig = lane & 3;

    const uint32_t uAh = smem_u32(sAh), uAl = smem_u32(sAl);
    const uint32_t uBh = smem_u32(sBh), uBl = smem_u32(sBl);

    float acc[2][8][4] = {};

    #pragma unroll
    for (int k0 = 0; k0 < KD; k0 += 16) {
        uint32_t ah[2][4], al[2][4];
        #pragma unroll
        for (int i = 0; i < 2; i++) {
            ldm_x4(ah[i], a_addr(uAh, wm + i * 16, k0, ST, lane));
            ldm_x4(al[i], a_addr(uAl, wm + i * 16, k0, ST, lane));
        }
        #pragma unroll
        for (int jj = 0; jj < 8; jj += 2) {
            uint32_t bhf[4], blf[4];
            ldm_x4(bhf, b_addr(uBh, wn + jj * 8, k0, ST, lane));
            ldm_x4(blf, b_addr(uBl, wn + jj * 8, k0, ST, lane));
            #pragma unroll
            for (int i = 0; i < 2; i++) {
                mma_bf16(acc[i][jj], ah[i], bhf[0], bhf[1]);
                mma_bf16(acc[i][jj], ah[i], blf[0], blf[1]);
                mma_bf16(acc[i][jj], al[i], bhf[0], bhf[1]);
                mma_bf16(acc[i][jj + 1], ah[i], bhf[2], bhf[3]);
                mma_bf16(acc[i][jj + 1], ah[i], blf[2], blf[3]);
                mma_bf16(acc[i][jj + 1], al[i], bhf[2], bhf[3]);
            }
        }
    }

    // Scale (branch 1 only; branch 2 pre-scaled in W)
    if (MODE == 0) {
        #pragma unroll
        for (int i = 0; i < 2; i++)
            #pragma unroll
            for (int j = 0; j < 8; j++)
                #pragma unroll
                for (int c = 0; c < 4; c++)
                    acc[i][j][c] *= SCALE_;
    }

    // Per-tile softmax stats over this warp's 64-wide n-slab.
    float2* ts = (MODE == 0) ? g_ts1 : g_ts2;
    const int nt = (n0 + wn) >> 6;
    #pragma unroll
    for (int i = 0; i < 2; i++) {
        float mlo = -1e30f, mhi = -1e30f;
        #pragma unroll
        for (int j = 0; j < 8; j++) {
            mlo = fmaxf(mlo, fmaxf(acc[i][j][0], acc[i][j][1]));
            mhi = fmaxf(mhi, fmaxf(acc[i][j][2], acc[i][j][3]));
        }
        #pragma unroll
        for (int o = 1; o <= 2; o <<= 1) {
            mlo = fmaxf(mlo, __shfl_xor_sync(0xffffffffu, mlo, o));
            mhi = fmaxf(mhi, __shfl_xor_sync(0xffffffffu, mhi, o));
        }
        float slo = 0.f, shi = 0.f;
        #pragma unroll
        for (int j = 0; j < 8; j++) {
            slo += __expf(acc[i][j][0] - mlo) + __expf(acc[i][j][1] - mlo);
            shi += __expf(acc[i][j][2] - mhi) + __expf(acc[i][j][3] - mhi);
        }
        #pragma unroll
        for (int o = 1; o <= 2; o <<= 1) {
            slo += __shfl_xor_sync(0xffffffffu, slo, o);
            shi += __shfl_xor_sync(0xffffffffu, shi, o);
        }
        if (tig == 0) {
            int rlo = q0 + wm + i * 16 + gid;
            ts[((size_t)bh * L_ + rlo) * 16 + nt] = make_float2(mlo, slo);
            ts[((size_t)bh * L_ + rlo + 8) * 16 + nt] = make_float2(mhi, shi);
        }
    }

    // Store logits tile
    float* out = (MODE == 0) ? g_l1 : l2out;
    #pragma unroll
    for (int i = 0; i < 2; i++) {
        #pragma unroll
        for (int j = 0; j < 8; j++) {
            int m = q0 + wm + i * 16 + gid;
            int n = n0 + wn + j * 8 + tig * 2;
            *(float2*)(out + ((size_t)bh * L_ + m) * L_ + n) =
                make_float2(acc[i][j][0], acc[i][j][1]);
            *(float2*)(out + ((size_t)bh * L_ + m + 8) * L_ + n) =
                make_float2(acc[i][j][2], acc[i][j][3]);
        }
    }
}

// ---------------------------------------------------------------------------
// Stats reduce: per row per branch, combine 16 tile stats -> (M, 1/S)
// ---------------------------------------------------------------------------
__global__ void stats_reduce_kernel() {
    int tid = blockIdx.x * blockDim.x + threadIdx.x;   // 2 * NROWS_
    int branch = tid >> 17;
    int row = tid & (NROWS_ - 1);
    const float2* ts = branch ? g_ts2 : g_ts1;
    float2* out = branch ? g_stat2 : g_stat1;
    float2 buf[16];
    float M = -1e30f;
    #pragma unroll
    for (int i = 0; i < 16; i++) {
        buf[i] = ts[(size_t)row * 16 + i];
        M = fmaxf(M, buf[i].x);
    }
    float S = 0.f;
    #pragma unroll
    for (int i = 0; i < 16; i++)
        S += buf[i].y * __expf(buf[i].x - M);
    out[row] = make_float2(M, 1.f / S);
}

// ---------------------------------------------------------------------------
// Fused: attn = exp(l1-M1)/S1 + exp(l2-M2)/S2 (write) and ctx += attn @ V (MMA)
// CTA: (q0=128, bh); k loop 16 x 64.
// ---------------------------------------------------------------------------
__global__ void __launch_bounds__(256) fused_attn_av_kernel(float* __restrict__ attn,
                                                            float* __restrict__ ctx) {
    constexpr int ST = 72;
    extern __shared__ __align__(16) __nv_bfloat16 sm[];
    __nv_bfloat16* sAh = sm;                       // 128 x ST
    __nv_bfloat16* sAl = sm + 128 * ST;
    __nv_bfloat16* sVh = sm + 2 * 128 * ST;        // 64 x ST
    __nv_bfloat16* sVl = sm + 2 * 128 * ST + 64 * ST;
    float* sStat = (float*)(sm + 2 * 128 * ST + 2 * 64 * ST);  // M1,I1,M2,I2 x128

    const int t = threadIdx.x;
    const int bh = blockIdx.y;
    const int q0 = blockIdx.x << 7;

    if (t < 128) {
        float2 s1 = g_stat1[bh * L_ + q0 + t];
        float2 s2 = g_stat2[bh * L_ + q0 + t];
        sStat[t] = s1.x; sStat[128 + t] = s1.y;
        sStat[256 + t] = s2.x; sStat[384 + t] = s2.y;
    }
    __syncthreads();

    const int w = t >> 5, lane = t & 31;
    const int wm = (w >> 1) << 5;    // 0..96
    const int wn = (w & 1) << 5;     // 0,32
    const int gid = lane >> 2, tig = lane & 3;

    const uint32_t uAh = smem_u32(sAh), uAl = smem_u32(sAl);
    const uint32_t uVh = smem_u32(sVh), uVl = smem_u32(sVl);

    float acc[2][4][4] = {};

    for (int kt = 0; kt < 16; kt++) {
        const int k0 = kt << 6;
        const float* l1p = g_l1 + ((size_t)bh * L_ + q0) * L_ + k0;
        const float* l2p = attn + ((size_t)bh * L_ + q0) * L_ + k0;
        float* aout = attn + ((size_t)bh * L_ + q0) * L_ + k0;

        #pragma unroll
        for (int i = 0; i < 8; i++) {
            int lin = t + i * 256;           // 2048 float4 slots
            int row = lin >> 4, pc = lin & 15;
            float4 x1 = *(const float4*)(l1p + (size_t)row * L_ + pc * 4);
            float4 x2 = *(const float4*)(l2p + (size_t)row * L_ + pc * 4);
            float M1 = sStat[row], I1 = sStat[128 + row];
            float M2 = sStat[256 + row], I2 = sStat[384 + row];
            float f[4];
            f[0] = __expf(x1.x - M1) * I1 + __expf(x2.x - M2) * I2;
            f[1] = __expf(x1.y - M1) * I1 + __expf(x2.y - M2) * I2;
            f[2] = __expf(x1.z - M1) * I1 + __expf(x2.z - M2) * I2;
            f[3] = __expf(x1.w - M1) * I1 + __expf(x2.w - M2) * I2;
            *(float4*)(aout + (size_t)row * L_ + pc * 4) = make_float4(f[0], f[1], f[2], f[3]);
            uint2 hp, lp;
            split_pack4(f, hp, lp);
            *(uint2*)(sAh + row * ST + pc * 4) = hp;
            *(uint2*)(sAl + row * ST + pc * 4) = lp;
        }
        #pragma unroll
        for (int i = 0; i < 4; i++) {
            int lin = t + i * 256;           // 1024 chunks: 2 tiles x 64 rows x 8
            int tile = lin >> 9, r = (lin >> 3) & 63, pc = lin & 7;
            const __nv_bfloat16* vs =
                (tile ? g_Vtl : g_Vth) + ((size_t)bh * DK_ + r) * L_ + k0 + pc * 8;
            __nv_bfloat16* vd = (tile ? sVl : sVh) + r * ST + pc * 8;
            *(uint4*)vd = *(const uint4*)vs;
        }
        __syncthreads();

        #pragma unroll
        for (int k1 = 0; k1 < 64; k1 += 16) {
            uint32_t ah[2][4], al[2][4];
            #pragma unroll
            for (int i = 0; i < 2; i++) {
                ldm_x4(ah[i], a_addr(uAh, wm + i * 16, k1, ST, lane));
                ldm_x4(al[i], a_addr(uAl, wm + i * 16, k1, ST, lane));
            }
            #pragma unroll
            for (int jj = 0; jj < 4; jj += 2) {
                uint32_t bhf[4], blf[4];
                ldm_x4(bhf, b_addr(uVh, wn + jj * 8, k1, ST, lane));
                ldm_x4(blf, b_addr(uVl, wn + jj * 8, k1, ST, lane));
                #pragma unroll
                for (int i = 0; i < 2; i++) {
                    mma_bf16(acc[i][jj], ah[i], bhf[0], bhf[1]);
                    mma_bf16(acc[i][jj], ah[i], blf[0], blf[1]);
                    mma_bf16(acc[i][jj], al[i], bhf[0], bhf[1]);
                    mma_bf16(acc[i][jj + 1], ah[i], bhf[2], bhf[3]);
                    mma_bf16(acc[i][jj + 1], ah[i], blf[2], blf[3]);
                    mma_bf16(acc[i][jj + 1], al[i], bhf[2], bhf[3]);
                }
            }
        }
        __syncthreads();
    }

    #pragma unroll
    for (int i = 0; i < 2; i++)
        #pragma unroll
        for (int j = 0; j < 4; j++) {
            int m = q0 + wm + i * 16 + gid;
            int n = wn + j * 8 + tig * 2;
            *(float2*)(ctx + ((size_t)bh * L_ + m) * DK_ + n) =
                make_float2(acc[i][j][0], acc[i][j][1]);
            *(float2*)(ctx + ((size_t)bh * L_ + m + 8) * DK_ + n) =
                make_float2(acc[i][j][2], acc[i][j][3]);
        }
}

// ---------------------------------------------------------------------------
extern "C" void kernel_launch(void* const* d_in, const int* in_sizes, int n_in,
                              void* d_out, int out_size) {
    const float* Q = (const float*)d_in[0];
    const float* K = (const float*)d_in[1];
    const float* V = (const float*)d_in[2];
    const float* W = (const float*)d_in[3];
    float* ctx  = (float*)d_out;                    // [B,H,L,Dv]
    float* attn = ctx + (size_t)BH_ * L_ * DK_;     // [B,H,L,L]

    // Prep
    cat_kernel<<<BH_ * L_ * 32 / 256, 256>>>(Q, K);
    wsplit_kernel<<<H_ * L_ * 32 / 256, 256>>>(W);
    vtrans_kernel<<<dim3(L_ / 64, BH_), 256>>>(V);

    // Logits + tile stats
    const int smem0 = 4 * 128 * (64 + 8) * 2;   // 73,728
    const int smem1 = 4 * 128 * (128 + 8) * 2;  // 139,264
    cudaFuncSetAttribute(mm_logits_kernel<0>,
                         cudaFuncAttributeMaxDynamicSharedMemorySize, smem0);
    cudaFuncSetAttribute(mm_logits_kernel<1>,
                         cudaFuncAttributeMaxDynamicSharedMemorySize, smem1);
    mm_logits_kernel<0><<<dim3(8, 8, BH_), 256, smem0>>>(attn);
    mm_logits_kernel<1><<<dim3(8, 8, BH_), 256, smem1>>>(attn);

    // Row stats
    stats_reduce_kernel<<<2 * NROWS_ / 256, 256>>>();

    // Fused softmax-add + AV
    const int smemF = (2 * 128 * 72 + 2 * 64 * 72) * 2 + 4 * 128 * 4;  // 57,344
    cudaFuncSetAttribute(fused_attn_av_kernel,
                         cudaFuncAttributeMaxDynamicSharedMemorySize, smemF);
    fused_attn_av_kernel<<<dim3(8, BH_), 256, smemF>>>(attn, ctx);
}

// round 5
// speedup vs baseline: 1.9409x; 1.9409x over previous
#include <cuda_runtime.h>
#include <cuda_bf16.h>
#include <cstdint>

#define B_  16
#define H_  8
#define L_  1024
#define DK_ 64
#define BH_ 128
#define NROWS_ (BH_ * L_)
#define SCALE_ 0.125f

// ---------------------------------------------------------------------------
// Device scratch
// ---------------------------------------------------------------------------
__device__ float g_l1[(size_t)BH_ * L_ * L_];
__device__ __nv_bfloat16 g_cath[(size_t)BH_ * L_ * 128];  // [bh][row][Q|K]
__device__ __nv_bfloat16 g_catl[(size_t)BH_ * L_ * 128];
__device__ __nv_bfloat16 g_Wh[(size_t)H_ * L_ * 128];     // pre-scaled by 0.125
__device__ __nv_bfloat16 g_Wl[(size_t)H_ * L_ * 128];
__device__ __nv_bfloat16 g_Vth[(size_t)BH_ * DK_ * L_];   // [bh][d][k]
__device__ __nv_bfloat16 g_Vtl[(size_t)BH_ * DK_ * L_];
__device__ float2 g_ts1[(size_t)NROWS_ * 16];             // per (row, 64-tile) (m, s)
__device__ float2 g_ts2[(size_t)NROWS_ * 16];
__device__ float2 g_stat1[NROWS_];                        // per row (M, 1/S)
__device__ float2 g_stat2[NROWS_];

// ---------------------------------------------------------------------------
// Helpers
// ---------------------------------------------------------------------------
__device__ __forceinline__ void mma_bf16(float (&c)[4], const uint32_t (&a)[4],
                                         const uint32_t (&b)[2]) {
    asm volatile(
        "mma.sync.aligned.m16n8k16.row.col.f32.bf16.bf16.f32 "
        "{%0,%1,%2,%3}, {%4,%5,%6,%7}, {%8,%9}, {%0,%1,%2,%3};\n"
        : "+f"(c[0]), "+f"(c[1]), "+f"(c[2]), "+f"(c[3])
        : "r"(a[0]), "r"(a[1]), "r"(a[2]), "r"(a[3]), "r"(b[0]), "r"(b[1]));
}

__device__ __forceinline__ void split_pack4(const float* f, uint2& hp, uint2& lp) {
    unsigned short* hw = (unsigned short*)&hp;
    unsigned short* lw = (unsigned short*)&lp;
    #pragma unroll
    for (int k = 0; k < 4; k++) {
        __nv_bfloat16 hb = __float2bfloat16(f[k]);
        float r = f[k] - __bfloat162float(hb);
        hw[k] = __bfloat16_as_ushort(hb);
        lw[k] = __bfloat16_as_ushort(__float2bfloat16(r));
    }
}

// ---------------------------------------------------------------------------
// Prep kernels
// ---------------------------------------------------------------------------
__global__ void cat_kernel(const float* __restrict__ Q, const float* __restrict__ K) {
    int tid = blockIdx.x * blockDim.x + threadIdx.x;
    int q = tid & 31;
    size_t row = (size_t)(tid >> 5);
    const float* src = (q < 16) ? (Q + row * 64 + q * 4)
                                : (K + row * 64 + (q - 16) * 4);
    int col = (q < 16) ? q * 4 : 64 + (q - 16) * 4;
    float4 v = *(const float4*)src;
    float f[4] = {v.x, v.y, v.z, v.w};
    uint2 hp, lp;
    split_pack4(f, hp, lp);
    *(uint2*)(g_cath + row * 128 + col) = hp;
    *(uint2*)(g_catl + row * 128 + col) = lp;
}

__global__ void wsplit_kernel(const float* __restrict__ W) {
    int tid = blockIdx.x * blockDim.x + threadIdx.x;
    float4 v = ((const float4*)W)[tid];
    float f[4] = {v.x * SCALE_, v.y * SCALE_, v.z * SCALE_, v.w * SCALE_};
    uint2 hp, lp;
    split_pack4(f, hp, lp);
    *(uint2*)(g_Wh + (size_t)tid * 4) = hp;
    *(uint2*)(g_Wl + (size_t)tid * 4) = lp;
}

__global__ void vtrans_kernel(const float* __restrict__ V) {
    __shared__ float tile[64][65];
    int bh = blockIdx.y, k0 = blockIdx.x << 6, t = threadIdx.x;
    const float* src = V + ((size_t)bh * L_ + k0) * DK_;
    #pragma unroll
    for (int i = 0; i < 16; i++) {
        int lin = t + i * 256;
        int r = lin >> 6, d = lin & 63;
        tile[r][d] = src[r * DK_ + d];
    }
    __syncthreads();
    #pragma unroll
    for (int i = 0; i < 16; i++) {
        int lin = t + i * 256;
        int d = lin >> 6, c = lin & 63;
        float x = tile[c][d];
        __nv_bfloat16 hb = __float2bfloat16(x);
        float r = x - __bfloat162float(hb);
        size_t o = ((size_t)bh * DK_ + d) * L_ + k0 + c;
        g_Vth[o] = hb;
        g_Vtl[o] = __float2bfloat16(r);
    }
}

// ---------------------------------------------------------------------------
// Logits GEMM (R3 inner loop) + per-tile softmax stats epilogue.
// MODE 0: l1 = Q.K^T (K=64); MODE 1: l2 = W.cat^T (K=128)
// ---------------------------------------------------------------------------
template <int MODE>
__global__ void __launch_bounds__(256) mm_logits_kernel(float* __restrict__ l2out) {
    constexpr int KD = (MODE == 0) ? 64 : 128;
    constexpr int ST = KD + 8;
    extern __shared__ __align__(16) __nv_bfloat16 sm[];
    __nv_bfloat16* sAh = sm;
    __nv_bfloat16* sAl = sm + 128 * ST;
    __nv_bfloat16* sBh = sm + 2 * 128 * ST;
    __nv_bfloat16* sBl = sm + 3 * 128 * ST;

    const int t = threadIdx.x;
    const int bh = blockIdx.z, h = bh & (H_ - 1);
    const int q0 = blockIdx.x << 7;
    const int n0 = blockIdx.y << 7;

    const __nv_bfloat16 *Ah, *Al, *Bh, *Bl;
    if (MODE == 0) {
        size_t base = (size_t)bh * L_ * 128;
        Ah = g_cath + base + (size_t)q0 * 128;
        Al = g_catl + base + (size_t)q0 * 128;
        Bh = g_cath + base + (size_t)n0 * 128 + 64;
        Bl = g_catl + base + (size_t)n0 * 128 + 64;
    } else {
        Ah = g_Wh + ((size_t)h * L_ + q0) * 128;
        Al = g_Wl + ((size_t)h * L_ + q0) * 128;
        Bh = g_cath + ((size_t)bh * L_ + n0) * 128;
        Bl = g_catl + ((size_t)bh * L_ + n0) * 128;
    }

    constexpr int CPR = KD / 8;
    constexpr int ITERS = 128 * CPR / 256;
    #pragma unroll
    for (int i = 0; i < ITERS; i++) {
        int lin = t + i * 256;
        int row = lin / CPR, pc = lin % CPR;
        *(uint4*)(sAh + row * ST + pc * 8) = *(const uint4*)(Ah + (size_t)row * 128 + pc * 8);
        *(uint4*)(sAl + row * ST + pc * 8) = *(const uint4*)(Al + (size_t)row * 128 + pc * 8);
        *(uint4*)(sBh + row * ST + pc * 8) = *(const uint4*)(Bh + (size_t)row * 128 + pc * 8);
        *(uint4*)(sBl + row * ST + pc * 8) = *(const uint4*)(Bl + (size_t)row * 128 + pc * 8);
    }
    __syncthreads();

    const int w = t >> 5, lane = t & 31;
    const int wm = (w >> 1) << 5;          // 0,32,64,96
    const int wn = (w & 1) << 6;           // 0,64
    const int gid = lane >> 2, tig = lane & 3;

    float acc[2][8][4] = {};

    #pragma unroll
    for (int k0 = 0; k0 < KD; k0 += 16) {
        uint32_t ah[2][4], al[2][4];
        #pragma unroll
        for (int i = 0; i < 2; i++) {
            int r = wm + i * 16 + gid;
            ah[i][0] = *(const uint32_t*)(sAh + r * ST + k0 + tig * 2);
            ah[i][1] = *(const uint32_t*)(sAh + (r + 8) * ST + k0 + tig * 2);
            ah[i][2] = *(const uint32_t*)(sAh + r * ST + k0 + tig * 2 + 8);
            ah[i][3] = *(const uint32_t*)(sAh + (r + 8) * ST + k0 + tig * 2 + 8);
            al[i][0] = *(const uint32_t*)(sAl + r * ST + k0 + tig * 2);
            al[i][1] = *(const uint32_t*)(sAl + (r + 8) * ST + k0 + tig * 2);
            al[i][2] = *(const uint32_t*)(sAl + r * ST + k0 + tig * 2 + 8);
            al[i][3] = *(const uint32_t*)(sAl + (r + 8) * ST + k0 + tig * 2 + 8);
        }
        uint32_t bhf[8][2], blf[8][2];
        #pragma unroll
        for (int j = 0; j < 8; j++) {
            int r = wn + j * 8 + gid;
            bhf[j][0] = *(const uint32_t*)(sBh + r * ST + k0 + tig * 2);
            bhf[j][1] = *(const uint32_t*)(sBh + r * ST + k0 + tig * 2 + 8);
            blf[j][0] = *(const uint32_t*)(sBl + r * ST + k0 + tig * 2);
            blf[j][1] = *(const uint32_t*)(sBl + r * ST + k0 + tig * 2 + 8);
        }
        #pragma unroll
        for (int i = 0; i < 2; i++)
            #pragma unroll
            for (int j = 0; j < 8; j++) {
                mma_bf16(acc[i][j], ah[i], bhf[j]);
                mma_bf16(acc[i][j], ah[i], blf[j]);
                mma_bf16(acc[i][j], al[i], bhf[j]);
            }
    }

    // Scale (branch 1 only; branch 2 pre-scaled in W)
    if (MODE == 0) {
        #pragma unroll
        for (int i = 0; i < 2; i++)
            #pragma unroll
            for (int j = 0; j < 8; j++)
                #pragma unroll
                for (int c = 0; c < 4; c++)
                    acc[i][j][c] *= SCALE_;
    }

    // Per-tile softmax stats over this warp's 64-wide n-slab (proven in R4).
    float2* ts = (MODE == 0) ? g_ts1 : g_ts2;
    const int nt = (n0 + wn) >> 6;
    #pragma unroll
    for (int i = 0; i < 2; i++) {
        float mlo = -1e30f, mhi = -1e30f;
        #pragma unroll
        for (int j = 0; j < 8; j++) {
            mlo = fmaxf(mlo, fmaxf(acc[i][j][0], acc[i][j][1]));
            mhi = fmaxf(mhi, fmaxf(acc[i][j][2], acc[i][j][3]));
        }
        #pragma unroll
        for (int o = 1; o <= 2; o <<= 1) {
            mlo = fmaxf(mlo, __shfl_xor_sync(0xffffffffu, mlo, o));
            mhi = fmaxf(mhi, __shfl_xor_sync(0xffffffffu, mhi, o));
        }
        float slo = 0.f, shi = 0.f;
        #pragma unroll
        for (int j = 0; j < 8; j++) {
            slo += __expf(acc[i][j][0] - mlo) + __expf(acc[i][j][1] - mlo);
            shi += __expf(acc[i][j][2] - mhi) + __expf(acc[i][j][3] - mhi);
        }
        #pragma unroll
        for (int o = 1; o <= 2; o <<= 1) {
            slo += __shfl_xor_sync(0xffffffffu, slo, o);
            shi += __shfl_xor_sync(0xffffffffu, shi, o);
        }
        if (tig == 0) {
            int rlo = q0 + wm + i * 16 + gid;
            ts[((size_t)bh * L_ + rlo) * 16 + nt] = make_float2(mlo, slo);
            ts[((size_t)bh * L_ + rlo + 8) * 16 + nt] = make_float2(mhi, shi);
        }
    }

    // Store logits tile
    float* out = (MODE == 0) ? g_l1 : l2out;
    #pragma unroll
    for (int i = 0; i < 2; i++) {
        #pragma unroll
        for (int j = 0; j < 8; j++) {
            int m = q0 + wm + i * 16 + gid;
            int n = n0 + wn + j * 8 + tig * 2;
            *(float2*)(out + ((size_t)bh * L_ + m) * L_ + n) =
                make_float2(acc[i][j][0], acc[i][j][1]);
            *(float2*)(out + ((size_t)bh * L_ + m + 8) * L_ + n) =
                make_float2(acc[i][j][2], acc[i][j][3]);
        }
    }
}

// ---------------------------------------------------------------------------
// Stats reduce: per row per branch, combine 16 tile stats -> (M, 1/S)
// ---------------------------------------------------------------------------
__global__ void stats_reduce_kernel() {
    int tid = blockIdx.x * blockDim.x + threadIdx.x;   // 2 * NROWS_
    int branch = tid >> 17;
    int row = tid & (NROWS_ - 1);
    const float2* ts = branch ? g_ts2 : g_ts1;
    float2* out = branch ? g_stat2 : g_stat1;
    float2 buf[16];
    float M = -1e30f;
    #pragma unroll
    for (int i = 0; i < 16; i++) {
        buf[i] = ts[(size_t)row * 16 + i];
        M = fmaxf(M, buf[i].x);
    }
    float S = 0.f;
    #pragma unroll
    for (int i = 0; i < 16; i++)
        S += buf[i].y * __expf(buf[i].x - M);
    out[row] = make_float2(M, 1.f / S);
}

// ---------------------------------------------------------------------------
// Fused: attn = exp(l1-M1)/S1 + exp(l2-M2)/S2 (streamed write) + ctx = attn@V
// 512 threads, 16 warps (8x2), warp tile 16x32. R3 scalar-LDS MMA loop.
// ---------------------------------------------------------------------------
__global__ void __launch_bounds__(512) fused_attn_av_kernel(float* __restrict__ attn,
                                                            float* __restrict__ ctx) {
    constexpr int ST = 72;
    extern __shared__ __align__(16) __nv_bfloat16 sm[];
    __nv_bfloat16* sAh = sm;                       // 128 x ST
    __nv_bfloat16* sAl = sm + 128 * ST;
    __nv_bfloat16* sVh = sm + 2 * 128 * ST;        // 64 x ST
    __nv_bfloat16* sVl = sm + 2 * 128 * ST + 64 * ST;
    float* sStat = (float*)(sm + 2 * 128 * ST + 2 * 64 * ST);  // M1,I1,M2,I2 x128

    const int t = threadIdx.x;
    const int bh = blockIdx.y;
    const int q0 = blockIdx.x << 7;

    if (t < 128) {
        float2 s1 = g_stat1[bh * L_ + q0 + t];
        float2 s2 = g_stat2[bh * L_ + q0 + t];
        sStat[t] = s1.x; sStat[128 + t] = s1.y;
        sStat[256 + t] = s2.x; sStat[384 + t] = s2.y;
    }
    __syncthreads();

    const int w = t >> 5, lane = t & 31;
    const int wm = (w >> 1) << 4;    // 0..112 (16-row slabs)
    const int wn = (w & 1) << 5;     // 0,32
    const int gid = lane >> 2, tig = lane & 3;

    float acc[4][4] = {};

    for (int kt = 0; kt < 16; kt++) {
        const int k0 = kt << 6;
        const float* l1p = g_l1 + ((size_t)bh * L_ + q0) * L_ + k0;
        float* l2p = attn + ((size_t)bh * L_ + q0) * L_ + k0;

        // Load logits, exp-combine, stream attn out, split to smem.
        #pragma unroll
        for (int i = 0; i < 4; i++) {
            int lin = t + i * 512;           // 2048 float4 slots
            int row = lin >> 4, pc = lin & 15;
            float4 x1 = *(const float4*)(l1p + (size_t)row * L_ + pc * 4);
            float4 x2 = *(const float4*)(l2p + (size_t)row * L_ + pc * 4);
            float M1 = sStat[row], I1 = sStat[128 + row];
            float M2 = sStat[256 + row], I2 = sStat[384 + row];
            float f[4];
            f[0] = __expf(x1.x - M1) * I1 + __expf(x2.x - M2) * I2;
            f[1] = __expf(x1.y - M1) * I1 + __expf(x2.y - M2) * I2;
            f[2] = __expf(x1.z - M1) * I1 + __expf(x2.z - M2) * I2;
            f[3] = __expf(x1.w - M1) * I1 + __expf(x2.w - M2) * I2;
            __stcs((float4*)(l2p + (size_t)row * L_ + pc * 4),
                   make_float4(f[0], f[1], f[2], f[3]));
            uint2 hp, lp;
            split_pack4(f, hp, lp);
            *(uint2*)(sAh + row * ST + pc * 4) = hp;
            *(uint2*)(sAl + row * ST + pc * 4) = lp;
        }
        #pragma unroll
        for (int i = 0; i < 2; i++) {
            int lin = t + i * 512;           // 1024 chunks: 2 tiles x 64 rows x 8
            int tile = lin >> 9, r = (lin >> 3) & 63, pc = lin & 7;
            const __nv_bfloat16* vs =
                (tile ? g_Vtl : g_Vth) + ((size_t)bh * DK_ + r) * L_ + k0 + pc * 8;
            __nv_bfloat16* vd = (tile ? sVl : sVh) + r * ST + pc * 8;
            *(uint4*)vd = *(const uint4*)vs;
        }
        __syncthreads();

        #pragma unroll
        for (int k1 = 0; k1 < 64; k1 += 16) {
            uint32_t ah[4], al[4];
            {
                int r = wm + gid;
                ah[0] = *(const uint32_t*)(sAh + r * ST + k1 + tig * 2);
                ah[1] = *(const uint32_t*)(sAh + (r + 8) * ST + k1 + tig * 2);
                ah[2] = *(const uint32_t*)(sAh + r * ST + k1 + tig * 2 + 8);
                ah[3] = *(const uint32_t*)(sAh + (r + 8) * ST + k1 + tig * 2 + 8);
                al[0] = *(const uint32_t*)(sAl + r * ST + k1 + tig * 2);
                al[1] = *(const uint32_t*)(sAl + (r + 8) * ST + k1 + tig * 2);
                al[2] = *(const uint32_t*)(sAl + r * ST + k1 + tig * 2 + 8);
                al[3] = *(const uint32_t*)(sAl + (r + 8) * ST + k1 + tig * 2 + 8);
            }
            uint32_t bhf[4][2], blf[4][2];
            #pragma unroll
            for (int j = 0; j < 4; j++) {
                int r = wn + j * 8 + gid;
                bhf[j][0] = *(const uint32_t*)(sVh + r * ST + k1 + tig * 2);
                bhf[j][1] = *(const uint32_t*)(sVh + r * ST + k1 + tig * 2 + 8);
                blf[j][0] = *(const uint32_t*)(sVl + r * ST + k1 + tig * 2);
                blf[j][1] = *(const uint32_t*)(sVl + r * ST + k1 + tig * 2 + 8);
            }
            #pragma unroll
            for (int j = 0; j < 4; j++) {
                mma_bf16(acc[j], ah, bhf[j]);
                mma_bf16(acc[j], ah, blf[j]);
                mma_bf16(acc[j], al, bhf[j]);
            }
        }
        __syncthreads();
    }

    #pragma unroll
    for (int j = 0; j < 4; j++) {
        int m = q0 + wm + gid;
        int n = wn + j * 8 + tig * 2;
        *(float2*)(ctx + ((size_t)bh * L_ + m) * DK_ + n) =
            make_float2(acc[j][0], acc[j][1]);
        *(float2*)(ctx + ((size_t)bh * L_ + m + 8) * DK_ + n) =
            make_float2(acc[j][2], acc[j][3]);
    }
}

// ---------------------------------------------------------------------------
extern "C" void kernel_launch(void* const* d_in, const int* in_sizes, int n_in,
                              void* d_out, int out_size) {
    const float* Q = (const float*)d_in[0];
    const float* K = (const float*)d_in[1];
    const float* V = (const float*)d_in[2];
    const float* W = (const float*)d_in[3];
    float* ctx  = (float*)d_out;                    // [B,H,L,Dv]
    float* attn = ctx + (size_t)BH_ * L_ * DK_;     // [B,H,L,L]

    // Prep
    cat_kernel<<<BH_ * L_ * 32 / 256, 256>>>(Q, K);
    wsplit_kernel<<<H_ * L_ * 32 / 256, 256>>>(W);
    vtrans_kernel<<<dim3(L_ / 64, BH_), 256>>>(V);

    // Logits + tile stats
    const int smem0 = 4 * 128 * (64 + 8) * 2;   // 73,728
    const int smem1 = 4 * 128 * (128 + 8) * 2;  // 139,264
    cudaFuncSetAttribute(mm_logits_kernel<0>,
                         cudaFuncAttributeMaxDynamicSharedMemorySize, smem0);
    cudaFuncSetAttribute(mm_logits_kernel<1>,
                         cudaFuncAttributeMaxDynamicSharedMemorySize, smem1);
    mm_logits_kernel<0><<<dim3(8, 8, BH_), 256, smem0>>>(attn);
    mm_logits_kernel<1><<<dim3(8, 8, BH_), 256, smem1>>>(attn);

    // Row stats
    stats_reduce_kernel<<<2 * NROWS_ / 256, 256>>>();

    // Fused softmax-add + AV
    const int smemF = (2 * 128 * 72 + 2 * 64 * 72) * 2 + 512 * 4;  // 57,344
    cudaFuncSetAttribute(fused_attn_av_kernel,
                         cudaFuncAttributeMaxDynamicSharedMemorySize, smemF);
    fused_attn_av_kernel<<<dim3(8, BH_), 512, smemF>>>(attn, ctx);
}

// round 6
// speedup vs baseline: 2.2034x; 1.1352x over previous
#include <cuda_runtime.h>
#include <cuda_bf16.h>
#include <cstdint>

#define B_  16
#define H_  8
#define L_  1024
#define DK_ 64
#define BH_ 128
#define NROWS_ (BH_ * L_)
#define SCALE_ 0.125f

// ---------------------------------------------------------------------------
// Device scratch
// ---------------------------------------------------------------------------
__device__ float g_l1[(size_t)BH_ * L_ * L_];
__device__ __nv_bfloat16 g_cath[(size_t)BH_ * L_ * 128];  // [bh][row][Q|K]
__device__ __nv_bfloat16 g_catl[(size_t)BH_ * L_ * 128];
__device__ __nv_bfloat16 g_Wh[(size_t)H_ * L_ * 128];     // pre-scaled by 0.125
__device__ __nv_bfloat16 g_Wl[(size_t)H_ * L_ * 128];
__device__ __nv_bfloat16 g_Vth[(size_t)BH_ * DK_ * L_];   // [bh][d][k]
__device__ __nv_bfloat16 g_Vtl[(size_t)BH_ * DK_ * L_];
__device__ float2 g_stat1[NROWS_];                        // per row (M, 1/S)
__device__ float2 g_stat2[NROWS_];

// ---------------------------------------------------------------------------
// Helpers
// ---------------------------------------------------------------------------
__device__ __forceinline__ uint32_t smem_u32(const void* p) {
    uint32_t a;
    asm("{ .reg .u64 t; cvta.to.shared.u64 t, %1; cvt.u32.u64 %0, t; }" : "=r"(a) : "l"(p));
    return a;
}
__device__ __forceinline__ void cp16(uint32_t dst, const void* src) {
    asm volatile("cp.async.cg.shared.global [%0], [%1], 16;" :: "r"(dst), "l"(src));
}
#define CP_COMMIT() asm volatile("cp.async.commit_group;" ::: "memory")
#define CP_WAIT(N)  asm volatile("cp.async.wait_group %0;" :: "n"(N) : "memory")

__device__ __forceinline__ void mma_bf16(float (&c)[4], const uint32_t (&a)[4],
                                         const uint32_t (&b)[2]) {
    asm volatile(
        "mma.sync.aligned.m16n8k16.row.col.f32.bf16.bf16.f32 "
        "{%0,%1,%2,%3}, {%4,%5,%6,%7}, {%8,%9}, {%0,%1,%2,%3};\n"
        : "+f"(c[0]), "+f"(c[1]), "+f"(c[2]), "+f"(c[3])
        : "r"(a[0]), "r"(a[1]), "r"(a[2]), "r"(a[3]), "r"(b[0]), "r"(b[1]));
}

__device__ __forceinline__ void split_pack4(const float* f, uint2& hp, uint2& lp) {
    unsigned short* hw = (unsigned short*)&hp;
    unsigned short* lw = (unsigned short*)&lp;
    #pragma unroll
    for (int k = 0; k < 4; k++) {
        __nv_bfloat16 hb = __float2bfloat16(f[k]);
        float r = f[k] - __bfloat162float(hb);
        hw[k] = __bfloat16_as_ushort(hb);
        lw[k] = __bfloat16_as_ushort(__float2bfloat16(r));
    }
}

// ---------------------------------------------------------------------------
// Prep kernels
// ---------------------------------------------------------------------------
__global__ void cat_kernel(const float* __restrict__ Q, const float* __restrict__ K) {
    int tid = blockIdx.x * blockDim.x + threadIdx.x;
    int q = tid & 31;
    size_t row = (size_t)(tid >> 5);
    const float* src = (q < 16) ? (Q + row * 64 + q * 4)
                                : (K + row * 64 + (q - 16) * 4);
    int col = (q < 16) ? q * 4 : 64 + (q - 16) * 4;
    float4 v = *(const float4*)src;
    float f[4] = {v.x, v.y, v.z, v.w};
    uint2 hp, lp;
    split_pack4(f, hp, lp);
    *(uint2*)(g_cath + row * 128 + col) = hp;
    *(uint2*)(g_catl + row * 128 + col) = lp;
}

__global__ void wsplit_kernel(const float* __restrict__ W) {
    int tid = blockIdx.x * blockDim.x + threadIdx.x;
    float4 v = ((const float4*)W)[tid];
    float f[4] = {v.x * SCALE_, v.y * SCALE_, v.z * SCALE_, v.w * SCALE_};
    uint2 hp, lp;
    split_pack4(f, hp, lp);
    *(uint2*)(g_Wh + (size_t)tid * 4) = hp;
    *(uint2*)(g_Wl + (size_t)tid * 4) = lp;
}

__global__ void vtrans_kernel(const float* __restrict__ V) {
    __shared__ float tile[64][65];
    int bh = blockIdx.y, k0 = blockIdx.x << 6, t = threadIdx.x;
    const float* src = V + ((size_t)bh * L_ + k0) * DK_;
    #pragma unroll
    for (int i = 0; i < 16; i++) {
        int lin = t + i * 256;
        int r = lin >> 6, d = lin & 63;
        tile[r][d] = src[r * DK_ + d];
    }
    __syncthreads();
    #pragma unroll
    for (int i = 0; i < 16; i++) {
        int lin = t + i * 256;
        int d = lin >> 6, c = lin & 63;
        float x = tile[c][d];
        __nv_bfloat16 hb = __float2bfloat16(x);
        float r = x - __bfloat162float(hb);
        size_t o = ((size_t)bh * DK_ + d) * L_ + k0 + c;
        g_Vth[o] = hb;
        g_Vtl[o] = __float2bfloat16(r);
    }
}

// ---------------------------------------------------------------------------
// n-persistent logits GEMM + running row softmax stats.
// MODE 0: l1 = Q.K^T (KD=64).  MODE 1: l2 = W.cat^T (KD=128).
// Grid (8 q0-tiles, 128 bh). CTA loops 8 n-tiles with cp.async double-buffered B.
// ---------------------------------------------------------------------------
template <int MODE>
__global__ void __launch_bounds__(256) mm_logits_kernel(float* __restrict__ l2out) {
    constexpr int KD = (MODE == 0) ? 64 : 128;
    constexpr int ST = KD + 8;
    constexpr int TSZ = 128 * ST;              // bf16 elems per tile
    extern __shared__ __align__(16) __nv_bfloat16 sm[];
    __nv_bfloat16* sAh = sm;
    __nv_bfloat16* sAl = sm + TSZ;
    __nv_bfloat16* sB0 = sm + 2 * TSZ;         // buf0: hi tile then lo tile
    __nv_bfloat16* sB1 = sm + 4 * TSZ;         // buf1
    __shared__ float2 sStat[2][128];

    const int t = threadIdx.x;
    const int bh = blockIdx.y, h = bh & (H_ - 1);
    const int q0 = blockIdx.x << 7;

    const __nv_bfloat16 *Ah, *Al, *Bh, *Bl;
    if (MODE == 0) {
        size_t base = (size_t)bh * L_ * 128;
        Ah = g_cath + base + (size_t)q0 * 128;       // Q rows (cols 0:64)
        Al = g_catl + base + (size_t)q0 * 128;
        Bh = g_cath + base + 64;                     // K rows (cols 64:128)
        Bl = g_catl + base + 64;
    } else {
        Ah = g_Wh + ((size_t)h * L_ + q0) * 128;
        Al = g_Wl + ((size_t)h * L_ + q0) * 128;
        Bh = g_cath + (size_t)bh * L_ * 128;         // full cat rows
        Bl = g_catl + (size_t)bh * L_ * 128;
    }

    constexpr int CPR = KD / 8;                      // 16B chunks per row
    constexpr int ACH = 128 * CPR;                   // chunks per tile

    const uint32_t uA = smem_u32(sm);
    const uint32_t uB0 = smem_u32(sB0);
    const uint32_t uB1 = smem_u32(sB1);

    // A tiles via cp.async (group with B prefetch 0)
    #pragma unroll
    for (int i = 0; i < ACH / 256; i++) {
        int lin = t + i * 256;
        int row = lin / CPR, pc = lin % CPR;
        cp16(uA + (uint32_t)((row * ST + pc * 8) * 2), Ah + (size_t)row * 128 + pc * 8);
        cp16(uA + (uint32_t)((TSZ + row * ST + pc * 8) * 2), Al + (size_t)row * 128 + pc * 8);
    }
    // B prefetch tile 0
    #pragma unroll
    for (int i = 0; i < ACH / 256; i++) {
        int lin = t + i * 256;
        int row = lin / CPR, pc = lin % CPR;
        cp16(uB0 + (uint32_t)((row * ST + pc * 8) * 2), Bh + (size_t)row * 128 + pc * 8);
        cp16(uB0 + (uint32_t)((TSZ + row * ST + pc * 8) * 2), Bl + (size_t)row * 128 + pc * 8);
    }
    CP_COMMIT();

    const int w = t >> 5, lane = t & 31;
    const int wm = (w >> 1) << 5;          // 0,32,64,96
    const int wn = (w & 1) << 6;           // 0,64
    const int gid = lane >> 2, tig = lane & 3;

    // Running row stats: 4 rows per lane: (i=0,lo),(i=0,hi),(i=1,lo),(i=1,hi)
    float rm[4] = {-1e30f, -1e30f, -1e30f, -1e30f};
    float rs[4] = {0.f, 0.f, 0.f, 0.f};

    float* out = (MODE == 0) ? g_l1 : l2out;

    for (int nt = 0; nt < 8; nt++) {
        const int n0 = nt << 7;
        __nv_bfloat16* sBc = (nt & 1) ? sB1 : sB0;
        // Prefetch next B into other buffer (prev compute done: end-of-loop sync)
        if (nt < 7) {
            const uint32_t uBn = (nt & 1) ? uB0 : uB1;
            const size_t nb = (size_t)(n0 + 128) * 128;
            #pragma unroll
            for (int i = 0; i < ACH / 256; i++) {
                int lin = t + i * 256;
                int row = lin / CPR, pc = lin % CPR;
                cp16(uBn + (uint32_t)((row * ST + pc * 8) * 2), Bh + nb + (size_t)row * 128 + pc * 8);
                cp16(uBn + (uint32_t)((TSZ + row * ST + pc * 8) * 2), Bl + nb + (size_t)row * 128 + pc * 8);
            }
            CP_COMMIT();
            CP_WAIT(1);
        } else {
            CP_WAIT(0);
        }
        __syncthreads();

        __nv_bfloat16* sBh = sBc;
        __nv_bfloat16* sBl = sBc + TSZ;

        float acc[2][8][4] = {};
        #pragma unroll
        for (int k0 = 0; k0 < KD; k0 += 16) {
            uint32_t ah[2][4], al[2][4];
            #pragma unroll
            for (int i = 0; i < 2; i++) {
                int r = wm + i * 16 + gid;
                ah[i][0] = *(const uint32_t*)(sAh + r * ST + k0 + tig * 2);
                ah[i][1] = *(const uint32_t*)(sAh + (r + 8) * ST + k0 + tig * 2);
                ah[i][2] = *(const uint32_t*)(sAh + r * ST + k0 + tig * 2 + 8);
                ah[i][3] = *(const uint32_t*)(sAh + (r + 8) * ST + k0 + tig * 2 + 8);
                al[i][0] = *(const uint32_t*)(sAl + r * ST + k0 + tig * 2);
                al[i][1] = *(const uint32_t*)(sAl + (r + 8) * ST + k0 + tig * 2);
                al[i][2] = *(const uint32_t*)(sAl + r * ST + k0 + tig * 2 + 8);
                al[i][3] = *(const uint32_t*)(sAl + (r + 8) * ST + k0 + tig * 2 + 8);
            }
            uint32_t bhf[8][2], blf[8][2];
            #pragma unroll
            for (int j = 0; j < 8; j++) {
                int r = wn + j * 8 + gid;
                bhf[j][0] = *(const uint32_t*)(sBh + r * ST + k0 + tig * 2);
                bhf[j][1] = *(const uint32_t*)(sBh + r * ST + k0 + tig * 2 + 8);
                blf[j][0] = *(const uint32_t*)(sBl + r * ST + k0 + tig * 2);
                blf[j][1] = *(const uint32_t*)(sBl + r * ST + k0 + tig * 2 + 8);
            }
            #pragma unroll
            for (int i = 0; i < 2; i++)
                #pragma unroll
                for (int j = 0; j < 8; j++) {
                    mma_bf16(acc[i][j], ah[i], bhf[j]);
                    mma_bf16(acc[i][j], ah[i], blf[j]);
                    mma_bf16(acc[i][j], al[i], bhf[j]);
                }
        }

        if (MODE == 0) {
            #pragma unroll
            for (int i = 0; i < 2; i++)
                #pragma unroll
                for (int j = 0; j < 8; j++)
                    #pragma unroll
                    for (int c = 0; c < 4; c++)
                        acc[i][j][c] *= SCALE_;
        }

        // Slab stats + running update
        #pragma unroll
        for (int i = 0; i < 2; i++) {
            float mlo = -1e30f, mhi = -1e30f;
            #pragma unroll
            for (int j = 0; j < 8; j++) {
                mlo = fmaxf(mlo, fmaxf(acc[i][j][0], acc[i][j][1]));
                mhi = fmaxf(mhi, fmaxf(acc[i][j][2], acc[i][j][3]));
            }
            #pragma unroll
            for (int o = 1; o <= 2; o <<= 1) {
                mlo = fmaxf(mlo, __shfl_xor_sync(0xffffffffu, mlo, o));
                mhi = fmaxf(mhi, __shfl_xor_sync(0xffffffffu, mhi, o));
            }
            float slo = 0.f, shi = 0.f;
            #pragma unroll
            for (int j = 0; j < 8; j++) {
                slo += __expf(acc[i][j][0] - mlo) + __expf(acc[i][j][1] - mlo);
                shi += __expf(acc[i][j][2] - mhi) + __expf(acc[i][j][3] - mhi);
            }
            #pragma unroll
            for (int o = 1; o <= 2; o <<= 1) {
                slo += __shfl_xor_sync(0xffffffffu, slo, o);
                shi += __shfl_xor_sync(0xffffffffu, shi, o);
            }
            float nm = fmaxf(rm[i * 2], mlo);
            rs[i * 2] = rs[i * 2] * __expf(rm[i * 2] - nm) + slo * __expf(mlo - nm);
            rm[i * 2] = nm;
            nm = fmaxf(rm[i * 2 + 1], mhi);
            rs[i * 2 + 1] = rs[i * 2 + 1] * __expf(rm[i * 2 + 1] - nm) + shi * __expf(mhi - nm);
            rm[i * 2 + 1] = nm;
        }

        // Store logits tile
        #pragma unroll
        for (int i = 0; i < 2; i++) {
            #pragma unroll
            for (int j = 0; j < 8; j++) {
                int m = q0 + wm + i * 16 + gid;
                int n = n0 + wn + j * 8 + tig * 2;
                *(float2*)(out + ((size_t)bh * L_ + m) * L_ + n) =
                    make_float2(acc[i][j][0], acc[i][j][1]);
                *(float2*)(out + ((size_t)bh * L_ + m + 8) * L_ + n) =
                    make_float2(acc[i][j][2], acc[i][j][3]);
            }
        }
        __syncthreads();   // buffers free for next prefetch
    }

    // Combine warp-pair stats (wn=0 and wn=64 halves cover the full row)
    if (tig == 0) {
        int slot = (w & 1);
        #pragma unroll
        for (int i = 0; i < 2; i++) {
            sStat[slot][wm + i * 16 + gid] = make_float2(rm[i * 2], rs[i * 2]);
            sStat[slot][wm + i * 16 + 8 + gid] = make_float2(rm[i * 2 + 1], rs[i * 2 + 1]);
        }
    }
    __syncthreads();
    if (t < 128) {
        float2 a = sStat[0][t], b = sStat[1][t];
        float M = fmaxf(a.x, b.x);
        float S = a.y * __expf(a.x - M) + b.y * __expf(b.x - M);
        float2* st = (MODE == 0) ? g_stat1 : g_stat2;
        st[bh * L_ + q0 + t] = make_float2(M, 1.f / S);
    }
}

// ---------------------------------------------------------------------------
// Fused: attn = exp(l1-M1)/S1 + exp(l2-M2)/S2 (streamed write) + ctx = attn@V
// 512 threads, 16 warps (8x2), warp tile 16x32.
// ---------------------------------------------------------------------------
__global__ void __launch_bounds__(512) fused_attn_av_kernel(float* __restrict__ attn,
                                                            float* __restrict__ ctx) {
    constexpr int ST = 72;
    extern __shared__ __align__(16) __nv_bfloat16 sm[];
    __nv_bfloat16* sAh = sm;                       // 128 x ST
    __nv_bfloat16* sAl = sm + 128 * ST;
    __nv_bfloat16* sVh = sm + 2 * 128 * ST;        // 64 x ST
    __nv_bfloat16* sVl = sm + 2 * 128 * ST + 64 * ST;
    float* sStat = (float*)(sm + 2 * 128 * ST + 2 * 64 * ST);  // M1,I1,M2,I2 x128

    const int t = threadIdx.x;
    const int bh = blockIdx.y;
    const int q0 = blockIdx.x << 7;

    if (t < 128) {
        float2 s1 = g_stat1[bh * L_ + q0 + t];
        float2 s2 = g_stat2[bh * L_ + q0 + t];
        sStat[t] = s1.x; sStat[128 + t] = s1.y;
        sStat[256 + t] = s2.x; sStat[384 + t] = s2.y;
    }
    __syncthreads();

    const int w = t >> 5, lane = t & 31;
    const int wm = (w >> 1) << 4;    // 0..112 (16-row slabs)
    const int wn = (w & 1) << 5;     // 0,32
    const int gid = lane >> 2, tig = lane & 3;

    float acc[4][4] = {};

    for (int kt = 0; kt < 16; kt++) {
        const int k0 = kt << 6;
        const float* l1p = g_l1 + ((size_t)bh * L_ + q0) * L_ + k0;
        float* l2p = attn + ((size_t)bh * L_ + q0) * L_ + k0;

        #pragma unroll
        for (int i = 0; i < 4; i++) {
            int lin = t + i * 512;
            int row = lin >> 4, pc = lin & 15;
            float4 x1 = *(const float4*)(l1p + (size_t)row * L_ + pc * 4);
            float4 x2 = *(const float4*)(l2p + (size_t)row * L_ + pc * 4);
            float M1 = sStat[row], I1 = sStat[128 + row];
            float M2 = sStat[256 + row], I2 = sStat[384 + row];
            float f[4];
            f[0] = __expf(x1.x - M1) * I1 + __expf(x2.x - M2) * I2;
            f[1] = __expf(x1.y - M1) * I1 + __expf(x2.y - M2) * I2;
            f[2] = __expf(x1.z - M1) * I1 + __expf(x2.z - M2) * I2;
            f[3] = __expf(x1.w - M1) * I1 + __expf(x2.w - M2) * I2;
            __stcs((float4*)(l2p + (size_t)row * L_ + pc * 4),
                   make_float4(f[0], f[1], f[2], f[3]));
            uint2 hp, lp;
            split_pack4(f, hp, lp);
            *(uint2*)(sAh + row * ST + pc * 4) = hp;
            *(uint2*)(sAl + row * ST + pc * 4) = lp;
        }
        #pragma unroll
        for (int i = 0; i < 2; i++) {
            int lin = t + i * 512;
            int tile = lin >> 9, r = (lin >> 3) & 63, pc = lin & 7;
            const __nv_bfloat16* vs =
                (tile ? g_Vtl : g_Vth) + ((size_t)bh * DK_ + r) * L_ + k0 + pc * 8;
            __nv_bfloat16* vd = (tile ? sVl : sVh) + r * ST + pc * 8;
            *(uint4*)vd = *(const uint4*)vs;
        }
        __syncthreads();

        #pragma unroll
        for (int k1 = 0; k1 < 64; k1 += 16) {
            uint32_t ah[4], al[4];
            {
                int r = wm + gid;
                ah[0] = *(const uint32_t*)(sAh + r * ST + k1 + tig * 2);
                ah[1] = *(const uint32_t*)(sAh + (r + 8) * ST + k1 + tig * 2);
                ah[2] = *(const uint32_t*)(sAh + r * ST + k1 + tig * 2 + 8);
                ah[3] = *(const uint32_t*)(sAh + (r + 8) * ST + k1 + tig * 2 + 8);
                al[0] = *(const uint32_t*)(sAl + r * ST + k1 + tig * 2);
                al[1] = *(const uint32_t*)(sAl + (r + 8) * ST + k1 + tig * 2);
                al[2] = *(const uint32_t*)(sAl + r * ST + k1 + tig * 2 + 8);
                al[3] = *(const uint32_t*)(sAl + (r + 8) * ST + k1 + tig * 2 + 8);
            }
            uint32_t bhf[4][2], blf[4][2];
            #pragma unroll
            for (int j = 0; j < 4; j++) {
                int r = wn + j * 8 + gid;
                bhf[j][0] = *(const uint32_t*)(sVh + r * ST + k1 + tig * 2);
                bhf[j][1] = *(const uint32_t*)(sVh + r * ST + k1 + tig * 2 + 8);
                blf[j][0] = *(const uint32_t*)(sVl + r * ST + k1 + tig * 2);
                blf[j][1] = *(const uint32_t*)(sVl + r * ST + k1 + tig * 2 + 8);
            }
            #pragma unroll
            for (int j = 0; j < 4; j++) {
                mma_bf16(acc[j], ah, bhf[j]);
                mma_bf16(acc[j], ah, blf[j]);
                mma_bf16(acc[j], al, bhf[j]);
            }
        }
        __syncthreads();
    }

    #pragma unroll
    for (int j = 0; j < 4; j++) {
        int m = q0 + wm + gid;
        int n = wn + j * 8 + tig * 2;
        *(float2*)(ctx + ((size_t)bh * L_ + m) * DK_ + n) =
            make_float2(acc[j][0], acc[j][1]);
        *(float2*)(ctx + ((size_t)bh * L_ + m + 8) * DK_ + n) =
            make_float2(acc[j][2], acc[j][3]);
    }
}

// ---------------------------------------------------------------------------
extern "C" void kernel_launch(void* const* d_in, const int* in_sizes, int n_in,
                              void* d_out, int out_size) {
    const float* Q = (const float*)d_in[0];
    const float* K = (const float*)d_in[1];
    const float* V = (const float*)d_in[2];
    const float* W = (const float*)d_in[3];
    float* ctx  = (float*)d_out;                    // [B,H,L,Dv]
    float* attn = ctx + (size_t)BH_ * L_ * DK_;     // [B,H,L,L]

    // Prep
    cat_kernel<<<BH_ * L_ * 32 / 256, 256>>>(Q, K);
    wsplit_kernel<<<H_ * L_ * 32 / 256, 256>>>(W);
    vtrans_kernel<<<dim3(L_ / 64, BH_), 256>>>(V);

    // n-persistent logits (+ in-kernel row stats)
    const int smem0 = 6 * 128 * (64 + 8) * 2;    // 110,592
    const int smem1 = 6 * 128 * (128 + 8) * 2;   // 208,896
    cudaFuncSetAttribute(mm_logits_kernel<0>,
                         cudaFuncAttributeMaxDynamicSharedMemorySize, smem0);
    cudaFuncSetAttribute(mm_logits_kernel<1>,
                         cudaFuncAttributeMaxDynamicSharedMemorySize, smem1);
    mm_logits_kernel<0><<<dim3(8, BH_), 256, smem0>>>(attn);
    mm_logits_kernel<1><<<dim3(8, BH_), 256, smem1>>>(attn);

    // Fused softmax-add + AV
    const int smemF = (2 * 128 * 72 + 2 * 64 * 72) * 2 + 512 * 4;  // 57,344
    cudaFuncSetAttribute(fused_attn_av_kernel,
                         cudaFuncAttributeMaxDynamicSharedMemorySize, smemF);
    fused_attn_av_kernel<<<dim3(8, BH_), 512, smemF>>>(attn, ctx);
}

// round 7
// speedup vs baseline: 2.2186x; 1.0069x over previous
#include <cuda_runtime.h>
#include <cuda_bf16.h>
#include <cstdint>

#define B_  16
#define H_  8
#define L_  1024
#define DK_ 64
#define BH_ 128
#define NROWS_ (BH_ * L_)
#define SCALE_ 0.125f

// ---------------------------------------------------------------------------
// Device scratch
// ---------------------------------------------------------------------------
__device__ float g_l1[(size_t)BH_ * L_ * L_];
__device__ __nv_bfloat16 g_cath[(size_t)BH_ * L_ * 128];  // [bh][row][Q|K]
__device__ __nv_bfloat16 g_catl[(size_t)BH_ * L_ * 128];
__device__ __nv_bfloat16 g_Wh[(size_t)H_ * L_ * 128];     // pre-scaled by 0.125
__device__ __nv_bfloat16 g_Wl[(size_t)H_ * L_ * 128];
__device__ __nv_bfloat16 g_Vth[(size_t)BH_ * DK_ * L_];   // [bh][d][k]
__device__ __nv_bfloat16 g_Vtl[(size_t)BH_ * DK_ * L_];
__device__ float2 g_stat1[NROWS_];                        // per row (M, 1/S)
__device__ float2 g_stat2[NROWS_];

// ---------------------------------------------------------------------------
// Helpers
// ---------------------------------------------------------------------------
__device__ __forceinline__ uint32_t smem_u32(const void* p) {
    uint32_t a;
    asm("{ .reg .u64 t; cvta.to.shared.u64 t, %1; cvt.u32.u64 %0, t; }" : "=r"(a) : "l"(p));
    return a;
}
__device__ __forceinline__ void cp16(uint32_t dst, const void* src) {
    asm volatile("cp.async.cg.shared.global [%0], [%1], 16;" :: "r"(dst), "l"(src));
}
#define CP_COMMIT() asm volatile("cp.async.commit_group;" ::: "memory")
#define CP_WAIT(N)  asm volatile("cp.async.wait_group %0;" :: "n"(N) : "memory")

__device__ __forceinline__ void mma_bf16(float (&c)[4], const uint32_t (&a)[4],
                                         const uint32_t (&b)[2]) {
    asm volatile(
        "mma.sync.aligned.m16n8k16.row.col.f32.bf16.bf16.f32 "
        "{%0,%1,%2,%3}, {%4,%5,%6,%7}, {%8,%9}, {%0,%1,%2,%3};\n"
        : "+f"(c[0]), "+f"(c[1]), "+f"(c[2]), "+f"(c[3])
        : "r"(a[0]), "r"(a[1]), "r"(a[2]), "r"(a[3]), "r"(b[0]), "r"(b[1]));
}

__device__ __forceinline__ void split_pack4(const float* f, uint2& hp, uint2& lp) {
    unsigned short* hw = (unsigned short*)&hp;
    unsigned short* lw = (unsigned short*)&lp;
    #pragma unroll
    for (int k = 0; k < 4; k++) {
        __nv_bfloat16 hb = __float2bfloat16(f[k]);
        float r = f[k] - __bfloat162float(hb);
        hw[k] = __bfloat16_as_ushort(hb);
        lw[k] = __bfloat16_as_ushort(__float2bfloat16(r));
    }
}

// ---------------------------------------------------------------------------
// Prep kernels (unchanged)
// ---------------------------------------------------------------------------
__global__ void cat_kernel(const float* __restrict__ Q, const float* __restrict__ K) {
    int tid = blockIdx.x * blockDim.x + threadIdx.x;
    int q = tid & 31;
    size_t row = (size_t)(tid >> 5);
    const float* src = (q < 16) ? (Q + row * 64 + q * 4)
                                : (K + row * 64 + (q - 16) * 4);
    int col = (q < 16) ? q * 4 : 64 + (q - 16) * 4;
    float4 v = *(const float4*)src;
    float f[4] = {v.x, v.y, v.z, v.w};
    uint2 hp, lp;
    split_pack4(f, hp, lp);
    *(uint2*)(g_cath + row * 128 + col) = hp;
    *(uint2*)(g_catl + row * 128 + col) = lp;
}

__global__ void wsplit_kernel(const float* __restrict__ W) {
    int tid = blockIdx.x * blockDim.x + threadIdx.x;
    float4 v = ((const float4*)W)[tid];
    float f[4] = {v.x * SCALE_, v.y * SCALE_, v.z * SCALE_, v.w * SCALE_};
    uint2 hp, lp;
    split_pack4(f, hp, lp);
    *(uint2*)(g_Wh + (size_t)tid * 4) = hp;
    *(uint2*)(g_Wl + (size_t)tid * 4) = lp;
}

__global__ void vtrans_kernel(const float* __restrict__ V) {
    __shared__ float tile[64][65];
    int bh = blockIdx.y, k0 = blockIdx.x << 6, t = threadIdx.x;
    const float* src = V + ((size_t)bh * L_ + k0) * DK_;
    #pragma unroll
    for (int i = 0; i < 16; i++) {
        int lin = t + i * 256;
        int r = lin >> 6, d = lin & 63;
        tile[r][d] = src[r * DK_ + d];
    }
    __syncthreads();
    #pragma unroll
    for (int i = 0; i < 16; i++) {
        int lin = t + i * 256;
        int d = lin >> 6, c = lin & 63;
        float x = tile[c][d];
        __nv_bfloat16 hb = __float2bfloat16(x);
        float r = x - __bfloat162float(hb);
        size_t o = ((size_t)bh * DK_ + d) * L_ + k0 + c;
        g_Vth[o] = hb;
        g_Vtl[o] = __float2bfloat16(r);
    }
}

// ---------------------------------------------------------------------------
// n-persistent logits GEMM + running row softmax stats. 512 threads.
// MODE 0: l1 = Q.K^T (KD=64).  MODE 1: l2 = W.cat^T (KD=128).
// 16 warps (8 m-slabs x 2 n-halves), warp tile 16x64.
// ---------------------------------------------------------------------------
template <int MODE>
__global__ void __launch_bounds__(512) mm_logits_kernel(float* __restrict__ l2out) {
    constexpr int KD = (MODE == 0) ? 64 : 128;
    constexpr int ST = KD + 8;
    constexpr int TSZ = 128 * ST;
    extern __shared__ __align__(16) __nv_bfloat16 sm[];
    __nv_bfloat16* sAh = sm;
    __nv_bfloat16* sAl = sm + TSZ;
    __nv_bfloat16* sB0 = sm + 2 * TSZ;
    __nv_bfloat16* sB1 = sm + 4 * TSZ;
    __shared__ float2 sStat[2][128];

    const int t = threadIdx.x;
    const int bh = blockIdx.y, h = bh & (H_ - 1);
    const int q0 = blockIdx.x << 7;

    const __nv_bfloat16 *Ah, *Al, *Bh, *Bl;
    if (MODE == 0) {
        size_t base = (size_t)bh * L_ * 128;
        Ah = g_cath + base + (size_t)q0 * 128;
        Al = g_catl + base + (size_t)q0 * 128;
        Bh = g_cath + base + 64;
        Bl = g_catl + base + 64;
    } else {
        Ah = g_Wh + ((size_t)h * L_ + q0) * 128;
        Al = g_Wl + ((size_t)h * L_ + q0) * 128;
        Bh = g_cath + (size_t)bh * L_ * 128;
        Bl = g_catl + (size_t)bh * L_ * 128;
    }

    constexpr int CPR = KD / 8;
    constexpr int ACH = 128 * CPR;

    const uint32_t uA = smem_u32(sm);
    const uint32_t uB0 = smem_u32(sB0);
    const uint32_t uB1 = smem_u32(sB1);

    #pragma unroll
    for (int i = 0; i < ACH / 512; i++) {
        int lin = t + i * 512;
        int row = lin / CPR, pc = lin % CPR;
        cp16(uA + (uint32_t)((row * ST + pc * 8) * 2), Ah + (size_t)row * 128 + pc * 8);
        cp16(uA + (uint32_t)((TSZ + row * ST + pc * 8) * 2), Al + (size_t)row * 128 + pc * 8);
    }
    #pragma unroll
    for (int i = 0; i < ACH / 512; i++) {
        int lin = t + i * 512;
        int row = lin / CPR, pc = lin % CPR;
        cp16(uB0 + (uint32_t)((row * ST + pc * 8) * 2), Bh + (size_t)row * 128 + pc * 8);
        cp16(uB0 + (uint32_t)((TSZ + row * ST + pc * 8) * 2), Bl + (size_t)row * 128 + pc * 8);
    }
    CP_COMMIT();

    const int w = t >> 5, lane = t & 31;
    const int wm = (w >> 1) << 4;          // 0..112 (16-row slabs)
    const int wn = (w & 1) << 6;           // 0,64
    const int gid = lane >> 2, tig = lane & 3;

    // Running stats for 2 rows/lane: row wm+gid (lo) and wm+8+gid (hi)
    float rm[2] = {-1e30f, -1e30f};
    float rs[2] = {0.f, 0.f};

    float* out = (MODE == 0) ? g_l1 : l2out;

    for (int nt = 0; nt < 8; nt++) {
        const int n0 = nt << 7;
        __nv_bfloat16* sBc = (nt & 1) ? sB1 : sB0;
        if (nt < 7) {
            const uint32_t uBn = (nt & 1) ? uB0 : uB1;
            const size_t nb = (size_t)(n0 + 128) * 128;
            #pragma unroll
            for (int i = 0; i < ACH / 512; i++) {
                int lin = t + i * 512;
                int row = lin / CPR, pc = lin % CPR;
                cp16(uBn + (uint32_t)((row * ST + pc * 8) * 2), Bh + nb + (size_t)row * 128 + pc * 8);
                cp16(uBn + (uint32_t)((TSZ + row * ST + pc * 8) * 2), Bl + nb + (size_t)row * 128 + pc * 8);
            }
            CP_COMMIT();
            CP_WAIT(1);
        } else {
            CP_WAIT(0);
        }
        __syncthreads();

        __nv_bfloat16* sBhp = sBc;
        __nv_bfloat16* sBlp = sBc + TSZ;

        float acc[8][4] = {};
        #pragma unroll
        for (int k0 = 0; k0 < KD; k0 += 16) {
            uint32_t ah[4], al[4];
            {
                int r = wm + gid;
                ah[0] = *(const uint32_t*)(sAh + r * ST + k0 + tig * 2);
                ah[1] = *(const uint32_t*)(sAh + (r + 8) * ST + k0 + tig * 2);
                ah[2] = *(const uint32_t*)(sAh + r * ST + k0 + tig * 2 + 8);
                ah[3] = *(const uint32_t*)(sAh + (r + 8) * ST + k0 + tig * 2 + 8);
                al[0] = *(const uint32_t*)(sAl + r * ST + k0 + tig * 2);
                al[1] = *(const uint32_t*)(sAl + (r + 8) * ST + k0 + tig * 2);
                al[2] = *(const uint32_t*)(sAl + r * ST + k0 + tig * 2 + 8);
                al[3] = *(const uint32_t*)(sAl + (r + 8) * ST + k0 + tig * 2 + 8);
            }
            uint32_t bhf[8][2], blf[8][2];
            #pragma unroll
            for (int j = 0; j < 8; j++) {
                int r = wn + j * 8 + gid;
                bhf[j][0] = *(const uint32_t*)(sBhp + r * ST + k0 + tig * 2);
                bhf[j][1] = *(const uint32_t*)(sBhp + r * ST + k0 + tig * 2 + 8);
                blf[j][0] = *(const uint32_t*)(sBlp + r * ST + k0 + tig * 2);
                blf[j][1] = *(const uint32_t*)(sBlp + r * ST + k0 + tig * 2 + 8);
            }
            #pragma unroll
            for (int j = 0; j < 8; j++) {
                mma_bf16(acc[j], ah, bhf[j]);
                mma_bf16(acc[j], ah, blf[j]);
                mma_bf16(acc[j], al, bhf[j]);
            }
        }

        if (MODE == 0) {
            #pragma unroll
            for (int j = 0; j < 8; j++)
                #pragma unroll
                for (int c = 0; c < 4; c++)
                    acc[j][c] *= SCALE_;
        }

        // Slab stats + running update
        {
            float mlo = -1e30f, mhi = -1e30f;
            #pragma unroll
            for (int j = 0; j < 8; j++) {
                mlo = fmaxf(mlo, fmaxf(acc[j][0], acc[j][1]));
                mhi = fmaxf(mhi, fmaxf(acc[j][2], acc[j][3]));
            }
            #pragma unroll
            for (int o = 1; o <= 2; o <<= 1) {
                mlo = fmaxf(mlo, __shfl_xor_sync(0xffffffffu, mlo, o));
                mhi = fmaxf(mhi, __shfl_xor_sync(0xffffffffu, mhi, o));
            }
            float slo = 0.f, shi = 0.f;
            #pragma unroll
            for (int j = 0; j < 8; j++) {
                slo += __expf(acc[j][0] - mlo) + __expf(acc[j][1] - mlo);
                shi += __expf(acc[j][2] - mhi) + __expf(acc[j][3] - mhi);
            }
            #pragma unroll
            for (int o = 1; o <= 2; o <<= 1) {
                slo += __shfl_xor_sync(0xffffffffu, slo, o);
                shi += __shfl_xor_sync(0xffffffffu, shi, o);
            }
            float nm = fmaxf(rm[0], mlo);
            rs[0] = rs[0] * __expf(rm[0] - nm) + slo * __expf(mlo - nm);
            rm[0] = nm;
            nm = fmaxf(rm[1], mhi);
            rs[1] = rs[1] * __expf(rm[1] - nm) + shi * __expf(mhi - nm);
            rm[1] = nm;
        }

        #pragma unroll
        for (int j = 0; j < 8; j++) {
            int m = q0 + wm + gid;
            int n = n0 + wn + j * 8 + tig * 2;
            *(float2*)(out + ((size_t)bh * L_ + m) * L_ + n) =
                make_float2(acc[j][0], acc[j][1]);
            *(float2*)(out + ((size_t)bh * L_ + m + 8) * L_ + n) =
                make_float2(acc[j][2], acc[j][3]);
        }
        __syncthreads();
    }

    if (tig == 0) {
        int slot = (w & 1);
        sStat[slot][wm + gid] = make_float2(rm[0], rs[0]);
        sStat[slot][wm + 8 + gid] = make_float2(rm[1], rs[1]);
    }
    __syncthreads();
    if (t < 128) {
        float2 a = sStat[0][t], b = sStat[1][t];
        float M = fmaxf(a.x, b.x);
        float S = a.y * __expf(a.x - M) + b.y * __expf(b.x - M);
        float2* st = (MODE == 0) ? g_stat1 : g_stat2;
        st[bh * L_ + q0 + t] = make_float2(M, 1.f / S);
    }
}

// ---------------------------------------------------------------------------
// Fused softmax+AV with cp.async pipelined raw-logit staging.
// smem (bytes from base):
//   raw l1 buf0 @0 (32K), raw l2 buf0 @32K, raw l1 buf1 @64K, raw l2 buf1 @96K
//   Vh0 @128K (9216), Vl0 @+9216, Vh1, Vl1   (ST=72 rows of 144B)
//   sAh @164K (18432), sAl @+18432           -> ~200KB total
// ---------------------------------------------------------------------------
#define RAW1_(b) ((b) ? 65536 : 0)
#define RAW2_(b) ((b) ? 98304 : 32768)
#define VH_(b)   (131072 + (b) * 18432)
#define VL_(b)   (131072 + (b) * 18432 + 9216)
#define SAH_     167936
#define SAL_     (167936 + 18432)
#define SMEMF_   (167936 + 2 * 18432)

__global__ void __launch_bounds__(512) fused_attn_av_kernel(float* __restrict__ attn,
                                                            float* __restrict__ ctx) {
    constexpr int ST = 72;
    extern __shared__ __align__(16) char smb[];
    __shared__ float sStat[512];

    const int t = threadIdx.x;
    const int bh = blockIdx.y;
    const int q0 = blockIdx.x << 7;
    const uint32_t ub = smem_u32(smb);

    if (t < 128) {
        float2 s1 = g_stat1[bh * L_ + q0 + t];
        float2 s2 = g_stat2[bh * L_ + q0 + t];
        sStat[t] = s1.x; sStat[128 + t] = s1.y;
        sStat[256 + t] = s2.x; sStat[384 + t] = s2.y;
    }

    const float* l1base = g_l1 + ((size_t)bh * L_ + q0) * L_;
    float* l2base = attn + ((size_t)bh * L_ + q0) * L_;

    // Prefetch tile 0 (raw l1/l2 + V)
    {
        #pragma unroll
        for (int i = 0; i < 8; i++) {
            int lin = t + i * 512;               // 4096 chunks
            int tile = lin >> 11, idx = lin & 2047;
            int row = idx >> 4, pc = idx & 15;
            const float* src = (tile ? l2base : l1base) + (size_t)row * L_ + pc * 4;
            cp16(ub + (tile ? RAW2_(0) : RAW1_(0)) + idx * 16, src);
        }
        #pragma unroll
        for (int i = 0; i < 2; i++) {
            int lin = t + i * 512;               // 1024 chunks
            int tile = lin >> 9, r = (lin >> 3) & 63, pc = lin & 7;
            const __nv_bfloat16* vs =
                (tile ? g_Vtl : g_Vth) + ((size_t)bh * DK_ + r) * L_ + pc * 8;
            cp16(ub + (tile ? VL_(0) : VH_(0)) + r * 144 + pc * 16, vs);
        }
        CP_COMMIT();
    }

    const int w = t >> 5, lane = t & 31;
    const int wm = (w >> 1) << 4;    // 0..112
    const int wn = (w & 1) << 5;     // 0,32
    const int gid = lane >> 2, tig = lane & 3;

    __nv_bfloat16* sAh = (__nv_bfloat16*)(smb + SAH_);
    __nv_bfloat16* sAl = (__nv_bfloat16*)(smb + SAL_);

    float acc[4][4] = {};

    for (int kt = 0; kt < 16; kt++) {
        const int k0 = kt << 6;
        const int cur = kt & 1;
        // Prefetch kt+1 into other buffers, then wait for kt.
        if (kt < 15) {
            const int nxt = cur ^ 1;
            const int kn = k0 + 64;
            #pragma unroll
            for (int i = 0; i < 8; i++) {
                int lin = t + i * 512;
                int tile = lin >> 11, idx = lin & 2047;
                int row = idx >> 4, pc = idx & 15;
                const float* src = (tile ? l2base : l1base) + (size_t)row * L_ + kn + pc * 4;
                cp16(ub + (tile ? RAW2_(nxt) : RAW1_(nxt)) + idx * 16, src);
            }
            #pragma unroll
            for (int i = 0; i < 2; i++) {
                int lin = t + i * 512;
                int tile = lin >> 9, r = (lin >> 3) & 63, pc = lin & 7;
                const __nv_bfloat16* vs =
                    (tile ? g_Vtl : g_Vth) + ((size_t)bh * DK_ + r) * L_ + kn + pc * 8;
                cp16(ub + (tile ? VL_(nxt) : VH_(nxt)) + r * 144 + pc * 16, vs);
            }
            CP_COMMIT();
            CP_WAIT(1);
        } else {
            CP_WAIT(0);
        }
        __syncthreads();

        // Transform raw(kt): exp-combine, stream attn out, split to smem.
        const float* r1 = (const float*)(smb + RAW1_(cur));
        const float* r2 = (const float*)(smb + RAW2_(cur));
        #pragma unroll
        for (int i = 0; i < 4; i++) {
            int lin = t + i * 512;               // 2048 float4 slots
            int row = lin >> 4, pc = lin & 15;
            float4 x1 = *(const float4*)(r1 + lin * 4);
            float4 x2 = *(const float4*)(r2 + lin * 4);
            float M1 = sStat[row], I1 = sStat[128 + row];
            float M2 = sStat[256 + row], I2 = sStat[384 + row];
            float f[4];
            f[0] = __expf(x1.x - M1) * I1 + __expf(x2.x - M2) * I2;
            f[1] = __expf(x1.y - M1) * I1 + __expf(x2.y - M2) * I2;
            f[2] = __expf(x1.z - M1) * I1 + __expf(x2.z - M2) * I2;
            f[3] = __expf(x1.w - M1) * I1 + __expf(x2.w - M2) * I2;
            __stcs((float4*)(l2base + (size_t)row * L_ + k0 + pc * 4),
                   make_float4(f[0], f[1], f[2], f[3]));
            uint2 hp, lp;
            split_pack4(f, hp, lp);
            *(uint2*)(sAh + row * ST + pc * 4) = hp;
            *(uint2*)(sAl + row * ST + pc * 4) = lp;
        }
        __syncthreads();

        // MMA on split(kt) + V(cur)
        const __nv_bfloat16* sVh = (const __nv_bfloat16*)(smb + VH_(cur));
        const __nv_bfloat16* sVl = (const __nv_bfloat16*)(smb + VL_(cur));
        #pragma unroll
        for (int k1 = 0; k1 < 64; k1 += 16) {
            uint32_t ah[4], al[4];
            {
                int r = wm + gid;
                ah[0] = *(const uint32_t*)(sAh + r * ST + k1 + tig * 2);
                ah[1] = *(const uint32_t*)(sAh + (r + 8) * ST + k1 + tig * 2);
                ah[2] = *(const uint32_t*)(sAh + r * ST + k1 + tig * 2 + 8);
                ah[3] = *(const uint32_t*)(sAh + (r + 8) * ST + k1 + tig * 2 + 8);
                al[0] = *(const uint32_t*)(sAl + r * ST + k1 + tig * 2);
                al[1] = *(const uint32_t*)(sAl + (r + 8) * ST + k1 + tig * 2);
                al[2] = *(const uint32_t*)(sAl + r * ST + k1 + tig * 2 + 8);
                al[3] = *(const uint32_t*)(sAl + (r + 8) * ST + k1 + tig * 2 + 8);
            }
            uint32_t bhf[4][2], blf[4][2];
            #pragma unroll
            for (int j = 0; j < 4; j++) {
                int r = wn + j * 8 + gid;
                bhf[j][0] = *(const uint32_t*)(sVh + r * ST + k1 + tig * 2);
                bhf[j][1] = *(const uint32_t*)(sVh + r * ST + k1 + tig * 2 + 8);
                blf[j][0] = *(const uint32_t*)(sVl + r * ST + k1 + tig * 2);
                blf[j][1] = *(const uint32_t*)(sVl + r * ST + k1 + tig * 2 + 8);
            }
            #pragma unroll
            for (int j = 0; j < 4; j++) {
                mma_bf16(acc[j], ah, bhf[j]);
                mma_bf16(acc[j], ah, blf[j]);
                mma_bf16(acc[j], al, bhf[j]);
            }
        }
        __syncthreads();
    }

    #pragma unroll
    for (int j = 0; j < 4; j++) {
        int m = q0 + wm + gid;
        int n = wn + j * 8 + tig * 2;
        *(float2*)(ctx + ((size_t)bh * L_ + m) * DK_ + n) =
            make_float2(acc[j][0], acc[j][1]);
        *(float2*)(ctx + ((size_t)bh * L_ + m + 8) * DK_ + n) =
            make_float2(acc[j][2], acc[j][3]);
    }
}

// ---------------------------------------------------------------------------
extern "C" void kernel_launch(void* const* d_in, const int* in_sizes, int n_in,
                              void* d_out, int out_size) {
    const float* Q = (const float*)d_in[0];
    const float* K = (const float*)d_in[1];
    const float* V = (const float*)d_in[2];
    const float* W = (const float*)d_in[3];
    float* ctx  = (float*)d_out;                    // [B,H,L,Dv]
    float* attn = ctx + (size_t)BH_ * L_ * DK_;     // [B,H,L,L]

    // Prep
    cat_kernel<<<BH_ * L_ * 32 / 256, 256>>>(Q, K);
    wsplit_kernel<<<H_ * L_ * 32 / 256, 256>>>(W);
    vtrans_kernel<<<dim3(L_ / 64, BH_), 256>>>(V);

    // n-persistent logits (+ in-kernel row stats), 512 threads
    const int smem0 = 6 * 128 * (64 + 8) * 2;    // 110,592
    const int smem1 = 6 * 128 * (128 + 8) * 2;   // 208,896
    cudaFuncSetAttribute(mm_logits_kernel<0>,
                         cudaFuncAttributeMaxDynamicSharedMemorySize, smem0);
    cudaFuncSetAttribute(mm_logits_kernel<1>,
                         cudaFuncAttributeMaxDynamicSharedMemorySize, smem1);
    mm_logits_kernel<0><<<dim3(8, BH_), 512, smem0>>>(attn);
    mm_logits_kernel<1><<<dim3(8, BH_), 512, smem1>>>(attn);

    // Fused softmax-add + AV (cp.async pipelined)
    cudaFuncSetAttribute(fused_attn_av_kernel,
                         cudaFuncAttributeMaxDynamicSharedMemorySize, SMEMF_);
    fused_attn_av_kernel<<<dim3(8, BH_), 512, SMEMF_>>>(attn, ctx);
}

// round 8
// speedup vs baseline: 2.4029x; 1.0830x over previous
#include <cuda_runtime.h>
#include <cuda_bf16.h>
#include <cstdint>

#define B_  16
#define H_  8
#define L_  1024
#define DK_ 64
#define BH_ 128
#define NROWS_ (BH_ * L_)
#define SCALE_ 0.125f

// ---------------------------------------------------------------------------
// Device scratch
// ---------------------------------------------------------------------------
__device__ float g_l1[(size_t)BH_ * L_ * L_];
__device__ __nv_bfloat16 g_cath[(size_t)BH_ * L_ * 128];  // [bh][row][Q|K]
__device__ __nv_bfloat16 g_catl[(size_t)BH_ * L_ * 128];
__device__ __nv_bfloat16 g_Wh[(size_t)H_ * L_ * 128];     // pre-scaled by 0.125
__device__ __nv_bfloat16 g_Wl[(size_t)H_ * L_ * 128];
__device__ __nv_bfloat16 g_Vth[(size_t)BH_ * DK_ * L_];   // [bh][d][k]
__device__ __nv_bfloat16 g_Vtl[(size_t)BH_ * DK_ * L_];
__device__ float2 g_stat1[NROWS_];                        // per row (M, 1/S)
__device__ float2 g_stat2[NROWS_];

// ---------------------------------------------------------------------------
// Helpers
// ---------------------------------------------------------------------------
__device__ __forceinline__ uint32_t smem_u32(const void* p) {
    uint32_t a;
    asm("{ .reg .u64 t; cvta.to.shared.u64 t, %1; cvt.u32.u64 %0, t; }" : "=r"(a) : "l"(p));
    return a;
}
__device__ __forceinline__ void cp16(uint32_t dst, const void* src) {
    asm volatile("cp.async.cg.shared.global [%0], [%1], 16;" :: "r"(dst), "l"(src));
}
#define CP_COMMIT() asm volatile("cp.async.commit_group;" ::: "memory")
#define CP_WAIT(N)  asm volatile("cp.async.wait_group %0;" :: "n"(N) : "memory")

__device__ __forceinline__ void mma_bf16(float (&c)[4], const uint32_t (&a)[4],
                                         const uint32_t (&b)[2]) {
    asm volatile(
        "mma.sync.aligned.m16n8k16.row.col.f32.bf16.bf16.f32 "
        "{%0,%1,%2,%3}, {%4,%5,%6,%7}, {%8,%9}, {%0,%1,%2,%3};\n"
        : "+f"(c[0]), "+f"(c[1]), "+f"(c[2]), "+f"(c[3])
        : "r"(a[0]), "r"(a[1]), "r"(a[2]), "r"(a[3]), "r"(b[0]), "r"(b[1]));
}

__device__ __forceinline__ void split_pack4(const float* f, uint2& hp, uint2& lp) {
    unsigned short* hw = (unsigned short*)&hp;
    unsigned short* lw = (unsigned short*)&lp;
    #pragma unroll
    for (int k = 0; k < 4; k++) {
        __nv_bfloat16 hb = __float2bfloat16(f[k]);
        float r = f[k] - __bfloat162float(hb);
        hw[k] = __bfloat16_as_ushort(hb);
        lw[k] = __bfloat16_as_ushort(__float2bfloat16(r));
    }
}

// ---------------------------------------------------------------------------
// Prep kernels (unchanged)
// ---------------------------------------------------------------------------
__global__ void cat_kernel(const float* __restrict__ Q, const float* __restrict__ K) {
    int tid = blockIdx.x * blockDim.x + threadIdx.x;
    int q = tid & 31;
    size_t row = (size_t)(tid >> 5);
    const float* src = (q < 16) ? (Q + row * 64 + q * 4)
                                : (K + row * 64 + (q - 16) * 4);
    int col = (q < 16) ? q * 4 : 64 + (q - 16) * 4;
    float4 v = *(const float4*)src;
    float f[4] = {v.x, v.y, v.z, v.w};
    uint2 hp, lp;
    split_pack4(f, hp, lp);
    *(uint2*)(g_cath + row * 128 + col) = hp;
    *(uint2*)(g_catl + row * 128 + col) = lp;
}

__global__ void wsplit_kernel(const float* __restrict__ W) {
    int tid = blockIdx.x * blockDim.x + threadIdx.x;
    float4 v = ((const float4*)W)[tid];
    float f[4] = {v.x * SCALE_, v.y * SCALE_, v.z * SCALE_, v.w * SCALE_};
    uint2 hp, lp;
    split_pack4(f, hp, lp);
    *(uint2*)(g_Wh + (size_t)tid * 4) = hp;
    *(uint2*)(g_Wl + (size_t)tid * 4) = lp;
}

__global__ void vtrans_kernel(const float* __restrict__ V) {
    __shared__ float tile[64][65];
    int bh = blockIdx.y, k0 = blockIdx.x << 6, t = threadIdx.x;
    const float* src = V + ((size_t)bh * L_ + k0) * DK_;
    #pragma unroll
    for (int i = 0; i < 16; i++) {
        int lin = t + i * 256;
        int r = lin >> 6, d = lin & 63;
        tile[r][d] = src[r * DK_ + d];
    }
    __syncthreads();
    #pragma unroll
    for (int i = 0; i < 16; i++) {
        int lin = t + i * 256;
        int d = lin >> 6, c = lin & 63;
        float x = tile[c][d];
        __nv_bfloat16 hb = __float2bfloat16(x);
        float r = x - __bfloat162float(hb);
        size_t o = ((size_t)bh * DK_ + d) * L_ + k0 + c;
        g_Vth[o] = hb;
        g_Vtl[o] = __float2bfloat16(r);
    }
}

// ---------------------------------------------------------------------------
// n-persistent logits GEMM + running row softmax stats (R6 proven: 256 thr).
// MODE 0: l1 = Q.K^T (KD=64).  MODE 1: l2 = W.cat^T (KD=128).
// 8 warps (4 m-slabs x 2 n-halves), warp tile 32x64.
// ---------------------------------------------------------------------------
template <int MODE>
__global__ void __launch_bounds__(256) mm_logits_kernel(float* __restrict__ l2out) {
    constexpr int KD = (MODE == 0) ? 64 : 128;
    constexpr int ST = KD + 8;
    constexpr int TSZ = 128 * ST;
    extern __shared__ __align__(16) __nv_bfloat16 sm[];
    __nv_bfloat16* sAh = sm;
    __nv_bfloat16* sAl = sm + TSZ;
    __nv_bfloat16* sB0 = sm + 2 * TSZ;
    __nv_bfloat16* sB1 = sm + 4 * TSZ;
    __shared__ float2 sStat[2][128];

    const int t = threadIdx.x;
    const int bh = blockIdx.y, h = bh & (H_ - 1);
    const int q0 = blockIdx.x << 7;

    const __nv_bfloat16 *Ah, *Al, *Bh, *Bl;
    if (MODE == 0) {
        size_t base = (size_t)bh * L_ * 128;
        Ah = g_cath + base + (size_t)q0 * 128;
        Al = g_catl + base + (size_t)q0 * 128;
        Bh = g_cath + base + 64;
        Bl = g_catl + base + 64;
    } else {
        Ah = g_Wh + ((size_t)h * L_ + q0) * 128;
        Al = g_Wl + ((size_t)h * L_ + q0) * 128;
        Bh = g_cath + (size_t)bh * L_ * 128;
        Bl = g_catl + (size_t)bh * L_ * 128;
    }

    constexpr int CPR = KD / 8;
    constexpr int ACH = 128 * CPR;

    const uint32_t uA = smem_u32(sm);
    const uint32_t uB0 = smem_u32(sB0);
    const uint32_t uB1 = smem_u32(sB1);

    #pragma unroll
    for (int i = 0; i < ACH / 256; i++) {
        int lin = t + i * 256;
        int row = lin / CPR, pc = lin % CPR;
        cp16(uA + (uint32_t)((row * ST + pc * 8) * 2), Ah + (size_t)row * 128 + pc * 8);
        cp16(uA + (uint32_t)((TSZ + row * ST + pc * 8) * 2), Al + (size_t)row * 128 + pc * 8);
    }
    #pragma unroll
    for (int i = 0; i < ACH / 256; i++) {
        int lin = t + i * 256;
        int row = lin / CPR, pc = lin % CPR;
        cp16(uB0 + (uint32_t)((row * ST + pc * 8) * 2), Bh + (size_t)row * 128 + pc * 8);
        cp16(uB0 + (uint32_t)((TSZ + row * ST + pc * 8) * 2), Bl + (size_t)row * 128 + pc * 8);
    }
    CP_COMMIT();

    const int w = t >> 5, lane = t & 31;
    const int wm = (w >> 1) << 5;          // 0,32,64,96
    const int wn = (w & 1) << 6;           // 0,64
    const int gid = lane >> 2, tig = lane & 3;

    // Running row stats: 4 rows per lane: (i=0,lo),(i=0,hi),(i=1,lo),(i=1,hi)
    float rm[4] = {-1e30f, -1e30f, -1e30f, -1e30f};
    float rs[4] = {0.f, 0.f, 0.f, 0.f};

    float* out = (MODE == 0) ? g_l1 : l2out;

    for (int nt = 0; nt < 8; nt++) {
        const int n0 = nt << 7;
        __nv_bfloat16* sBc = (nt & 1) ? sB1 : sB0;
        if (nt < 7) {
            const uint32_t uBn = (nt & 1) ? uB0 : uB1;
            const size_t nb = (size_t)(n0 + 128) * 128;
            #pragma unroll
            for (int i = 0; i < ACH / 256; i++) {
                int lin = t + i * 256;
                int row = lin / CPR, pc = lin % CPR;
                cp16(uBn + (uint32_t)((row * ST + pc * 8) * 2), Bh + nb + (size_t)row * 128 + pc * 8);
                cp16(uBn + (uint32_t)((TSZ + row * ST + pc * 8) * 2), Bl + nb + (size_t)row * 128 + pc * 8);
            }
            CP_COMMIT();
            CP_WAIT(1);
        } else {
            CP_WAIT(0);
        }
        __syncthreads();

        __nv_bfloat16* sBhp = sBc;
        __nv_bfloat16* sBlp = sBc + TSZ;

        float acc[2][8][4] = {};
        #pragma unroll
        for (int k0 = 0; k0 < KD; k0 += 16) {
            uint32_t ah[2][4], al[2][4];
            #pragma unroll
            for (int i = 0; i < 2; i++) {
                int r = wm + i * 16 + gid;
                ah[i][0] = *(const uint32_t*)(sAh + r * ST + k0 + tig * 2);
                ah[i][1] = *(const uint32_t*)(sAh + (r + 8) * ST + k0 + tig * 2);
                ah[i][2] = *(const uint32_t*)(sAh + r * ST + k0 + tig * 2 + 8);
                ah[i][3] = *(const uint32_t*)(sAh + (r + 8) * ST + k0 + tig * 2 + 8);
                al[i][0] = *(const uint32_t*)(sAl + r * ST + k0 + tig * 2);
                al[i][1] = *(const uint32_t*)(sAl + (r + 8) * ST + k0 + tig * 2);
                al[i][2] = *(const uint32_t*)(sAl + r * ST + k0 + tig * 2 + 8);
                al[i][3] = *(const uint32_t*)(sAl + (r + 8) * ST + k0 + tig * 2 + 8);
            }
            uint32_t bhf[8][2], blf[8][2];
            #pragma unroll
            for (int j = 0; j < 8; j++) {
                int r = wn + j * 8 + gid;
                bhf[j][0] = *(const uint32_t*)(sBhp + r * ST + k0 + tig * 2);
                bhf[j][1] = *(const uint32_t*)(sBhp + r * ST + k0 + tig * 2 + 8);
                blf[j][0] = *(const uint32_t*)(sBlp + r * ST + k0 + tig * 2);
                blf[j][1] = *(const uint32_t*)(sBlp + r * ST + k0 + tig * 2 + 8);
            }
            #pragma unroll
            for (int i = 0; i < 2; i++)
                #pragma unroll
                for (int j = 0; j < 8; j++) {
                    mma_bf16(acc[i][j], ah[i], bhf[j]);
                    mma_bf16(acc[i][j], ah[i], blf[j]);
                    mma_bf16(acc[i][j], al[i], bhf[j]);
                }
        }

        if (MODE == 0) {
            #pragma unroll
            for (int i = 0; i < 2; i++)
                #pragma unroll
                for (int j = 0; j < 8; j++)
                    #pragma unroll
                    for (int c = 0; c < 4; c++)
                        acc[i][j][c] *= SCALE_;
        }

        // Slab stats + running update
        #pragma unroll
        for (int i = 0; i < 2; i++) {
            float mlo = -1e30f, mhi = -1e30f;
            #pragma unroll
            for (int j = 0; j < 8; j++) {
                mlo = fmaxf(mlo, fmaxf(acc[i][j][0], acc[i][j][1]));
                mhi = fmaxf(mhi, fmaxf(acc[i][j][2], acc[i][j][3]));
            }
            #pragma unroll
            for (int o = 1; o <= 2; o <<= 1) {
                mlo = fmaxf(mlo, __shfl_xor_sync(0xffffffffu, mlo, o));
                mhi = fmaxf(mhi, __shfl_xor_sync(0xffffffffu, mhi, o));
            }
            float slo = 0.f, shi = 0.f;
            #pragma unroll
            for (int j = 0; j < 8; j++) {
                slo += __expf(acc[i][j][0] - mlo) + __expf(acc[i][j][1] - mlo);
                shi += __expf(acc[i][j][2] - mhi) + __expf(acc[i][j][3] - mhi);
            }
            #pragma unroll
            for (int o = 1; o <= 2; o <<= 1) {
                slo += __shfl_xor_sync(0xffffffffu, slo, o);
                shi += __shfl_xor_sync(0xffffffffu, shi, o);
            }
            float nm = fmaxf(rm[i * 2], mlo);
            rs[i * 2] = rs[i * 2] * __expf(rm[i * 2] - nm) + slo * __expf(mlo - nm);
            rm[i * 2] = nm;
            nm = fmaxf(rm[i * 2 + 1], mhi);
            rs[i * 2 + 1] = rs[i * 2 + 1] * __expf(rm[i * 2 + 1] - nm) + shi * __expf(mhi - nm);
            rm[i * 2 + 1] = nm;
        }

        // Store logits tile
        #pragma unroll
        for (int i = 0; i < 2; i++) {
            #pragma unroll
            for (int j = 0; j < 8; j++) {
                int m = q0 + wm + i * 16 + gid;
                int n = n0 + wn + j * 8 + tig * 2;
                *(float2*)(out + ((size_t)bh * L_ + m) * L_ + n) =
                    make_float2(acc[i][j][0], acc[i][j][1]);
                *(float2*)(out + ((size_t)bh * L_ + m + 8) * L_ + n) =
                    make_float2(acc[i][j][2], acc[i][j][3]);
            }
        }
        __syncthreads();
    }

    if (tig == 0) {
        int slot = (w & 1);
        #pragma unroll
        for (int i = 0; i < 2; i++) {
            sStat[slot][wm + i * 16 + gid] = make_float2(rm[i * 2], rs[i * 2]);
            sStat[slot][wm + i * 16 + 8 + gid] = make_float2(rm[i * 2 + 1], rs[i * 2 + 1]);
        }
    }
    __syncthreads();
    if (t < 128) {
        float2 a = sStat[0][t], b = sStat[1][t];
        float M = fmaxf(a.x, b.x);
        float S = a.y * __expf(a.x - M) + b.y * __expf(b.x - M);
        float2* st = (MODE == 0) ? g_stat1 : g_stat2;
        st[bh * L_ + q0 + t] = make_float2(M, 1.f / S);
    }
}

// ---------------------------------------------------------------------------
// Fused softmax+AV with cp.async pipelined raw-logit staging (R7 proven).
// ---------------------------------------------------------------------------
#define RAW1_(b) ((b) ? 65536 : 0)
#define RAW2_(b) ((b) ? 98304 : 32768)
#define VH_(b)   (131072 + (b) * 18432)
#define VL_(b)   (131072 + (b) * 18432 + 9216)
#define SAH_     167936
#define SAL_     (167936 + 18432)
#define SMEMF_   (167936 + 2 * 18432)

__global__ void __launch_bounds__(512) fused_attn_av_kernel(float* __restrict__ attn,
                                                            float* __restrict__ ctx) {
    constexpr int ST = 72;
    extern __shared__ __align__(16) char smb[];
    __shared__ float sStat[512];

    const int t = threadIdx.x;
    const int bh = blockIdx.y;
    const int q0 = blockIdx.x << 7;
    const uint32_t ub = smem_u32(smb);

    if (t < 128) {
        float2 s1 = g_stat1[bh * L_ + q0 + t];
        float2 s2 = g_stat2[bh * L_ + q0 + t];
        sStat[t] = s1.x; sStat[128 + t] = s1.y;
        sStat[256 + t] = s2.x; sStat[384 + t] = s2.y;
    }

    const float* l1base = g_l1 + ((size_t)bh * L_ + q0) * L_;
    float* l2base = attn + ((size_t)bh * L_ + q0) * L_;

    // Prefetch tile 0 (raw l1/l2 + V)
    {
        #pragma unroll
        for (int i = 0; i < 8; i++) {
            int lin = t + i * 512;               // 4096 chunks
            int tile = lin >> 11, idx = lin & 2047;
            int row = idx >> 4, pc = idx & 15;
            const float* src = (tile ? l2base : l1base) + (size_t)row * L_ + pc * 4;
            cp16(ub + (tile ? RAW2_(0) : RAW1_(0)) + idx * 16, src);
        }
        #pragma unroll
        for (int i = 0; i < 2; i++) {
            int lin = t + i * 512;               // 1024 chunks
            int tile = lin >> 9, r = (lin >> 3) & 63, pc = lin & 7;
            const __nv_bfloat16* vs =
                (tile ? g_Vtl : g_Vth) + ((size_t)bh * DK_ + r) * L_ + pc * 8;
            cp16(ub + (tile ? VL_(0) : VH_(0)) + r * 144 + pc * 16, vs);
        }
        CP_COMMIT();
    }

    const int w = t >> 5, lane = t & 31;
    const int wm = (w >> 1) << 4;    // 0..112
    const int wn = (w & 1) << 5;     // 0,32
    const int gid = lane >> 2, tig = lane & 3;

    __nv_bfloat16* sAh = (__nv_bfloat16*)(smb + SAH_);
    __nv_bfloat16* sAl = (__nv_bfloat16*)(smb + SAL_);

    float acc[4][4] = {};

    for (int kt = 0; kt < 16; kt++) {
        const int k0 = kt << 6;
        const int cur = kt & 1;
        if (kt < 15) {
            const int nxt = cur ^ 1;
            const int kn = k0 + 64;
            #pragma unroll
            for (int i = 0; i < 8; i++) {
                int lin = t + i * 512;
                int tile = lin >> 11, idx = lin & 2047;
                int row = idx >> 4, pc = idx & 15;
                const float* src = (tile ? l2base : l1base) + (size_t)row * L_ + kn + pc * 4;
                cp16(ub + (tile ? RAW2_(nxt) : RAW1_(nxt)) + idx * 16, src);
            }
            #pragma unroll
            for (int i = 0; i < 2; i++) {
                int lin = t + i * 512;
                int tile = lin >> 9, r = (lin >> 3) & 63, pc = lin & 7;
                const __nv_bfloat16* vs =
                    (tile ? g_Vtl : g_Vth) + ((size_t)bh * DK_ + r) * L_ + kn + pc * 8;
                cp16(ub + (tile ? VL_(nxt) : VH_(nxt)) + r * 144 + pc * 16, vs);
            }
            CP_COMMIT();
            CP_WAIT(1);
        } else {
            CP_WAIT(0);
        }
        __syncthreads();

        // Transform raw(kt): exp-combine, stream attn out, split to smem.
        const float* r1 = (const float*)(smb + RAW1_(cur));
        const float* r2 = (const float*)(smb + RAW2_(cur));
        #pragma unroll
        for (int i = 0; i < 4; i++) {
            int lin = t + i * 512;               // 2048 float4 slots
            int row = lin >> 4, pc = lin & 15;
            float4 x1 = *(const float4*)(r1 + lin * 4);
            float4 x2 = *(const float4*)(r2 + lin * 4);
            float M1 = sStat[row], I1 = sStat[128 + row];
            float M2 = sStat[256 + row], I2 = sStat[384 + row];
            float f[4];
            f[0] = __expf(x1.x - M1) * I1 + __expf(x2.x - M2) * I2;
            f[1] = __expf(x1.y - M1) * I1 + __expf(x2.y - M2) * I2;
            f[2] = __expf(x1.z - M1) * I1 + __expf(x2.z - M2) * I2;
            f[3] = __expf(x1.w - M1) * I1 + __expf(x2.w - M2) * I2;
            __stcs((float4*)(l2base + (size_t)row * L_ + k0 + pc * 4),
                   make_float4(f[0], f[1], f[2], f[3]));
            uint2 hp, lp;
            split_pack4(f, hp, lp);
            *(uint2*)(sAh + row * ST + pc * 4) = hp;
            *(uint2*)(sAl + row * ST + pc * 4) = lp;
        }
        __syncthreads();

        // MMA on split(kt) + V(cur)
        const __nv_bfloat16* sVh = (const __nv_bfloat16*)(smb + VH_(cur));
        const __nv_bfloat16* sVl = (const __nv_bfloat16*)(smb + VL_(cur));
        #pragma unroll
        for (int k1 = 0; k1 < 64; k1 += 16) {
            uint32_t ah[4], al[4];
            {
                int r = wm + gid;
                ah[0] = *(const uint32_t*)(sAh + r * ST + k1 + tig * 2);
                ah[1] = *(const uint32_t*)(sAh + (r + 8) * ST + k1 + tig * 2);
                ah[2] = *(const uint32_t*)(sAh + r * ST + k1 + tig * 2 + 8);
                ah[3] = *(const uint32_t*)(sAh + (r + 8) * ST + k1 + tig * 2 + 8);
                al[0] = *(const uint32_t*)(sAl + r * ST + k1 + tig * 2);
                al[1] = *(const uint32_t*)(sAl + (r + 8) * ST + k1 + tig * 2);
                al[2] = *(const uint32_t*)(sAl + r * ST + k1 + tig * 2 + 8);
                al[3] = *(const uint32_t*)(sAl + (r + 8) * ST + k1 + tig * 2 + 8);
            }
            uint32_t bhf[4][2], blf[4][2];
            #pragma unroll
            for (int j = 0; j < 4; j++) {
                int r = wn + j * 8 + gid;
                bhf[j][0] = *(const uint32_t*)(sVh + r * ST + k1 + tig * 2);
                bhf[j][1] = *(const uint32_t*)(sVh + r * ST + k1 + tig * 2 + 8);
                blf[j][0] = *(const uint32_t*)(sVl + r * ST + k1 + tig * 2);
                blf[j][1] = *(const uint32_t*)(sVl + r * ST + k1 + tig * 2 + 8);
            }
            #pragma unroll
            for (int j = 0; j < 4; j++) {
                mma_bf16(acc[j], ah, bhf[j]);
                mma_bf16(acc[j], ah, blf[j]);
                mma_bf16(acc[j], al, bhf[j]);
            }
        }
        __syncthreads();
    }

    #pragma unroll
    for (int j = 0; j < 4; j++) {
        int m = q0 + wm + gid;
        int n = wn + j * 8 + tig * 2;
        *(float2*)(ctx + ((size_t)bh * L_ + m) * DK_ + n) =
            make_float2(acc[j][0], acc[j][1]);
        *(float2*)(ctx + ((size_t)bh * L_ + m + 8) * DK_ + n) =
            make_float2(acc[j][2], acc[j][3]);
    }
}

// ---------------------------------------------------------------------------
extern "C" void kernel_launch(void* const* d_in, const int* in_sizes, int n_in,
                              void* d_out, int out_size) {
    const float* Q = (const float*)d_in[0];
    const float* K = (const float*)d_in[1];
    const float* V = (const float*)d_in[2];
    const float* W = (const float*)d_in[3];
    float* ctx  = (float*)d_out;                    // [B,H,L,Dv]
    float* attn = ctx + (size_t)BH_ * L_ * DK_;     // [B,H,L,L]

    // Prep
    cat_kernel<<<BH_ * L_ * 32 / 256, 256>>>(Q, K);
    wsplit_kernel<<<H_ * L_ * 32 / 256, 256>>>(W);
    vtrans_kernel<<<dim3(L_ / 64, BH_), 256>>>(V);

    // n-persistent logits (+ in-kernel row stats), 256 threads (R6 config)
    const int smem0 = 6 * 128 * (64 + 8) * 2;    // 110,592
    const int smem1 = 6 * 128 * (128 + 8) * 2;   // 208,896
    cudaFuncSetAttribute(mm_logits_kernel<0>,
                         cudaFuncAttributeMaxDynamicSharedMemorySize, smem0);
    cudaFuncSetAttribute(mm_logits_kernel<1>,
                         cudaFuncAttributeMaxDynamicSharedMemorySize, smem1);
    mm_logits_kernel<0><<<dim3(8, BH_), 256, smem0>>>(attn);
    mm_logits_kernel<1><<<dim3(8, BH_), 256, smem1>>>(attn);

    // Fused softmax-add + AV (cp.async pipelined)
    cudaFuncSetAttribute(fused_attn_av_kernel,
                         cudaFuncAttributeMaxDynamicSharedMemorySize, SMEMF_);
    fused_attn_av_kernel<<<dim3(8, BH_), 512, SMEMF_>>>(attn, ctx);
}

// round 9
// speedup vs baseline: 2.4388x; 1.0150x over previous
#include <cuda_runtime.h>
#include <cuda_bf16.h>
#include <cstdint>

#define B_  16
#define H_  8
#define L_  1024
#define DK_ 64
#define BH_ 128
#define NROWS_ (BH_ * L_)
#define SCALE_ 0.125f

// ---------------------------------------------------------------------------
// Device scratch
// ---------------------------------------------------------------------------
__device__ float g_l1[(size_t)BH_ * L_ * L_];
__device__ __nv_bfloat16 g_cath[(size_t)BH_ * L_ * 128];  // [bh][row][Q|K]
__device__ __nv_bfloat16 g_catl[(size_t)BH_ * L_ * 128];
__device__ __nv_bfloat16 g_Wh[(size_t)H_ * L_ * 128];     // pre-scaled by 0.125
__device__ __nv_bfloat16 g_Wl[(size_t)H_ * L_ * 128];
__device__ __nv_bfloat16 g_Vth[(size_t)BH_ * DK_ * L_];   // [bh][d][k]
__device__ __nv_bfloat16 g_Vtl[(size_t)BH_ * DK_ * L_];
__device__ float2 g_stat1[NROWS_];                        // per row (M, 1/S)
__device__ float2 g_stat2[NROWS_];

// ---------------------------------------------------------------------------
// Helpers
// ---------------------------------------------------------------------------
__device__ __forceinline__ uint32_t smem_u32(const void* p) {
    uint32_t a;
    asm("{ .reg .u64 t; cvta.to.shared.u64 t, %1; cvt.u32.u64 %0, t; }" : "=r"(a) : "l"(p));
    return a;
}
__device__ __forceinline__ void cp16(uint32_t dst, const void* src) {
    asm volatile("cp.async.cg.shared.global [%0], [%1], 16;" :: "r"(dst), "l"(src));
}
#define CP_COMMIT() asm volatile("cp.async.commit_group;" ::: "memory")
#define CP_WAIT(N)  asm volatile("cp.async.wait_group %0;" :: "n"(N) : "memory")

__device__ __forceinline__ void mma_bf16(float (&c)[4], const uint32_t (&a)[4],
                                         const uint32_t b0, const uint32_t b1) {
    asm volatile(
        "mma.sync.aligned.m16n8k16.row.col.f32.bf16.bf16.f32 "
        "{%0,%1,%2,%3}, {%4,%5,%6,%7}, {%8,%9}, {%0,%1,%2,%3};\n"
        : "+f"(c[0]), "+f"(c[1]), "+f"(c[2]), "+f"(c[3])
        : "r"(a[0]), "r"(a[1]), "r"(a[2]), "r"(a[3]), "r"(b0), "r"(b1));
}

__device__ __forceinline__ void ldm_x4(uint32_t (&r)[4], uint32_t addr) {
    asm volatile("ldmatrix.sync.aligned.m8n8.x4.shared.b16 {%0,%1,%2,%3}, [%4];"
                 : "=r"(r[0]), "=r"(r[1]), "=r"(r[2]), "=r"(r[3]) : "r"(addr));
}

__device__ __forceinline__ void split_pack4(const float* f, uint2& hp, uint2& lp) {
    unsigned short* hw = (unsigned short*)&hp;
    unsigned short* lw = (unsigned short*)&lp;
    #pragma unroll
    for (int k = 0; k < 4; k++) {
        __nv_bfloat16 hb = __float2bfloat16(f[k]);
        float r = f[k] - __bfloat162float(hb);
        hw[k] = __bfloat16_as_ushort(hb);
        lw[k] = __bfloat16_as_ushort(__float2bfloat16(r));
    }
}

// ---------------------------------------------------------------------------
// Prep kernels (unchanged)
// ---------------------------------------------------------------------------
__global__ void cat_kernel(const float* __restrict__ Q, const float* __restrict__ K) {
    int tid = blockIdx.x * blockDim.x + threadIdx.x;
    int q = tid & 31;
    size_t row = (size_t)(tid >> 5);
    const float* src = (q < 16) ? (Q + row * 64 + q * 4)
                                : (K + row * 64 + (q - 16) * 4);
    int col = (q < 16) ? q * 4 : 64 + (q - 16) * 4;
    float4 v = *(const float4*)src;
    float f[4] = {v.x, v.y, v.z, v.w};
    uint2 hp, lp;
    split_pack4(f, hp, lp);
    *(uint2*)(g_cath + row * 128 + col) = hp;
    *(uint2*)(g_catl + row * 128 + col) = lp;
}

__global__ void wsplit_kernel(const float* __restrict__ W) {
    int tid = blockIdx.x * blockDim.x + threadIdx.x;
    float4 v = ((const float4*)W)[tid];
    float f[4] = {v.x * SCALE_, v.y * SCALE_, v.z * SCALE_, v.w * SCALE_};
    uint2 hp, lp;
    split_pack4(f, hp, lp);
    *(uint2*)(g_Wh + (size_t)tid * 4) = hp;
    *(uint2*)(g_Wl + (size_t)tid * 4) = lp;
}

__global__ void vtrans_kernel(const float* __restrict__ V) {
    __shared__ float tile[64][65];
    int bh = blockIdx.y, k0 = blockIdx.x << 6, t = threadIdx.x;
    const float* src = V + ((size_t)bh * L_ + k0) * DK_;
    #pragma unroll
    for (int i = 0; i < 16; i++) {
        int lin = t + i * 256;
        int r = lin >> 6, d = lin & 63;
        tile[r][d] = src[r * DK_ + d];
    }
    __syncthreads();
    #pragma unroll
    for (int i = 0; i < 16; i++) {
        int lin = t + i * 256;
        int d = lin >> 6, c = lin & 63;
        float x = tile[c][d];
        __nv_bfloat16 hb = __float2bfloat16(x);
        float r = x - __bfloat162float(hb);
        size_t o = ((size_t)bh * DK_ + d) * L_ + k0 + c;
        g_Vth[o] = hb;
        g_Vtl[o] = __float2bfloat16(r);
    }
}

// ---------------------------------------------------------------------------
// n-persistent logits GEMM + running row softmax stats.
// 256 threads, 8 warps (4 m-slabs x 2 n-halves), warp tile 32x64.
// Fragment loads via grouped ldmatrix.x4 (all loads, THEN full MMA burst).
// MODE 0: l1 = Q.K^T (KD=64).  MODE 1: l2 = W.cat^T (KD=128).
// ---------------------------------------------------------------------------
template <int MODE>
__global__ void __launch_bounds__(256) mm_logits_kernel(float* __restrict__ l2out) {
    constexpr int KD = (MODE == 0) ? 64 : 128;
    constexpr int ST = KD + 8;
    constexpr int TSZ = 128 * ST;
    extern __shared__ __align__(16) __nv_bfloat16 sm[];
    __nv_bfloat16* sAh = sm;
    __nv_bfloat16* sAl = sm + TSZ;
    __nv_bfloat16* sB0 = sm + 2 * TSZ;
    __nv_bfloat16* sB1 = sm + 4 * TSZ;
    __shared__ float2 sStat[2][128];

    const int t = threadIdx.x;
    const int bh = blockIdx.y, h = bh & (H_ - 1);
    const int q0 = blockIdx.x << 7;

    const __nv_bfloat16 *Ah, *Al, *Bh, *Bl;
    if (MODE == 0) {
        size_t base = (size_t)bh * L_ * 128;
        Ah = g_cath + base + (size_t)q0 * 128;
        Al = g_catl + base + (size_t)q0 * 128;
        Bh = g_cath + base + 64;
        Bl = g_catl + base + 64;
    } else {
        Ah = g_Wh + ((size_t)h * L_ + q0) * 128;
        Al = g_Wl + ((size_t)h * L_ + q0) * 128;
        Bh = g_cath + (size_t)bh * L_ * 128;
        Bl = g_catl + (size_t)bh * L_ * 128;
    }

    constexpr int CPR = KD / 8;
    constexpr int ACH = 128 * CPR;

    const uint32_t uA = smem_u32(sm);
    const uint32_t uB0 = smem_u32(sB0);
    const uint32_t uB1 = smem_u32(sB1);

    #pragma unroll
    for (int i = 0; i < ACH / 256; i++) {
        int lin = t + i * 256;
        int row = lin / CPR, pc = lin % CPR;
        cp16(uA + (uint32_t)((row * ST + pc * 8) * 2), Ah + (size_t)row * 128 + pc * 8);
        cp16(uA + (uint32_t)((TSZ + row * ST + pc * 8) * 2), Al + (size_t)row * 128 + pc * 8);
    }
    #pragma unroll
    for (int i = 0; i < ACH / 256; i++) {
        int lin = t + i * 256;
        int row = lin / CPR, pc = lin % CPR;
        cp16(uB0 + (uint32_t)((row * ST + pc * 8) * 2), Bh + (size_t)row * 128 + pc * 8);
        cp16(uB0 + (uint32_t)((TSZ + row * ST + pc * 8) * 2), Bl + (size_t)row * 128 + pc * 8);
    }
    CP_COMMIT();

    const int w = t >> 5, lane = t & 31;
    const int wm = (w >> 1) << 5;          // 0,32,64,96
    const int wn = (w & 1) << 6;           // 0,64
    const int gid = lane >> 2, tig = lane & 3;

    // ldmatrix per-lane address components
    const int rowA = wm + (lane & 15);             // A: lanes 0-15 rows, 16-31 k+8
    const int kofA = (lane >> 4) << 3;
    const int nrB = wn + ((lane >> 4) << 3) + (lane & 7);  // B: n-row
    const int kofB = ((lane >> 3) & 1) << 3;

    const uint32_t uAh = smem_u32(sAh), uAl = smem_u32(sAl);

    // Running row stats: 4 rows per lane
    float rm[4] = {-1e30f, -1e30f, -1e30f, -1e30f};
    float rs[4] = {0.f, 0.f, 0.f, 0.f};

    float* out = (MODE == 0) ? g_l1 : l2out;

    for (int nt = 0; nt < 8; nt++) {
        const int n0 = nt << 7;
        __nv_bfloat16* sBc = (nt & 1) ? sB1 : sB0;
        if (nt < 7) {
            const uint32_t uBn = (nt & 1) ? uB0 : uB1;
            const size_t nb = (size_t)(n0 + 128) * 128;
            #pragma unroll
            for (int i = 0; i < ACH / 256; i++) {
                int lin = t + i * 256;
                int row = lin / CPR, pc = lin % CPR;
                cp16(uBn + (uint32_t)((row * ST + pc * 8) * 2), Bh + nb + (size_t)row * 128 + pc * 8);
                cp16(uBn + (uint32_t)((TSZ + row * ST + pc * 8) * 2), Bl + nb + (size_t)row * 128 + pc * 8);
            }
            CP_COMMIT();
            CP_WAIT(1);
        } else {
            CP_WAIT(0);
        }
        __syncthreads();

        const uint32_t uBh = (nt & 1) ? uB1 : uB0;
        const uint32_t uBl = uBh + TSZ * 2;

        float acc[2][8][4] = {};
        #pragma unroll
        for (int k0 = 0; k0 < KD; k0 += 16) {
            // --- ALL fragment loads (12 LDSM.x4), then full MMA burst ---
            uint32_t ah[2][4], al[2][4];
            #pragma unroll
            for (int i = 0; i < 2; i++) {
                uint32_t aoff = (uint32_t)(((rowA + i * 16) * ST + k0 + kofA) * 2);
                ldm_x4(ah[i], uAh + aoff);
                ldm_x4(al[i], uAl + aoff);
            }
            uint32_t bh4[4][4], bl4[4][4];   // [p] covers j=2p, 2p+1
            #pragma unroll
            for (int p = 0; p < 4; p++) {
                uint32_t boff = (uint32_t)(((nrB + p * 16) * ST + k0 + kofB) * 2);
                ldm_x4(bh4[p], uBh + boff);
                ldm_x4(bl4[p], uBl + boff);
            }
            #pragma unroll
            for (int i = 0; i < 2; i++)
                #pragma unroll
                for (int j = 0; j < 8; j++) {
                    const int p = j >> 1, q = (j & 1) << 1;
                    mma_bf16(acc[i][j], ah[i], bh4[p][q], bh4[p][q + 1]);
                    mma_bf16(acc[i][j], ah[i], bl4[p][q], bl4[p][q + 1]);
                    mma_bf16(acc[i][j], al[i], bh4[p][q], bh4[p][q + 1]);
                }
        }

        if (MODE == 0) {
            #pragma unroll
            for (int i = 0; i < 2; i++)
                #pragma unroll
                for (int j = 0; j < 8; j++)
                    #pragma unroll
                    for (int c = 0; c < 4; c++)
                        acc[i][j][c] *= SCALE_;
        }

        // Slab stats + running update
        #pragma unroll
        for (int i = 0; i < 2; i++) {
            float mlo = -1e30f, mhi = -1e30f;
            #pragma unroll
            for (int j = 0; j < 8; j++) {
                mlo = fmaxf(mlo, fmaxf(acc[i][j][0], acc[i][j][1]));
                mhi = fmaxf(mhi, fmaxf(acc[i][j][2], acc[i][j][3]));
            }
            #pragma unroll
            for (int o = 1; o <= 2; o <<= 1) {
                mlo = fmaxf(mlo, __shfl_xor_sync(0xffffffffu, mlo, o));
                mhi = fmaxf(mhi, __shfl_xor_sync(0xffffffffu, mhi, o));
            }
            float slo = 0.f, shi = 0.f;
            #pragma unroll
            for (int j = 0; j < 8; j++) {
                slo += __expf(acc[i][j][0] - mlo) + __expf(acc[i][j][1] - mlo);
                shi += __expf(acc[i][j][2] - mhi) + __expf(acc[i][j][3] - mhi);
            }
            #pragma unroll
            for (int o = 1; o <= 2; o <<= 1) {
                slo += __shfl_xor_sync(0xffffffffu, slo, o);
                shi += __shfl_xor_sync(0xffffffffu, shi, o);
            }
            float nm = fmaxf(rm[i * 2], mlo);
            rs[i * 2] = rs[i * 2] * __expf(rm[i * 2] - nm) + slo * __expf(mlo - nm);
            rm[i * 2] = nm;
            nm = fmaxf(rm[i * 2 + 1], mhi);
            rs[i * 2 + 1] = rs[i * 2 + 1] * __expf(rm[i * 2 + 1] - nm) + shi * __expf(mhi - nm);
            rm[i * 2 + 1] = nm;
        }

        // Store logits tile
        #pragma unroll
        for (int i = 0; i < 2; i++) {
            #pragma unroll
            for (int j = 0; j < 8; j++) {
                int m = q0 + wm + i * 16 + gid;
                int n = n0 + wn + j * 8 + tig * 2;
                *(float2*)(out + ((size_t)bh * L_ + m) * L_ + n) =
                    make_float2(acc[i][j][0], acc[i][j][1]);
                *(float2*)(out + ((size_t)bh * L_ + m + 8) * L_ + n) =
                    make_float2(acc[i][j][2], acc[i][j][3]);
            }
        }
        __syncthreads();
    }

    if (tig == 0) {
        int slot = (w & 1);
        #pragma unroll
        for (int i = 0; i < 2; i++) {
            sStat[slot][wm + i * 16 + gid] = make_float2(rm[i * 2], rs[i * 2]);
            sStat[slot][wm + i * 16 + 8 + gid] = make_float2(rm[i * 2 + 1], rs[i * 2 + 1]);
        }
    }
    __syncthreads();
    if (t < 128) {
        float2 a = sStat[0][t], b = sStat[1][t];
        float M = fmaxf(a.x, b.x);
        float S = a.y * __expf(a.x - M) + b.y * __expf(b.x - M);
        float2* st = (MODE == 0) ? g_stat1 : g_stat2;
        st[bh * L_ + q0 + t] = make_float2(M, 1.f / S);
    }
}

// ---------------------------------------------------------------------------
// Fused softmax+AV with cp.async pipelined raw-logit staging (R7/R8 proven).
// ---------------------------------------------------------------------------
#define RAW1_(b) ((b) ? 65536 : 0)
#define RAW2_(b) ((b) ? 98304 : 32768)
#define VH_(b)   (131072 + (b) * 18432)
#define VL_(b)   (131072 + (b) * 18432 + 9216)
#define SAH_     167936
#define SAL_     (167936 + 18432)
#define SMEMF_   (167936 + 2 * 18432)

__global__ void __launch_bounds__(512) fused_attn_av_kernel(float* __restrict__ attn,
                                                            float* __restrict__ ctx) {
    constexpr int ST = 72;
    extern __shared__ __align__(16) char smb[];
    __shared__ float sStat[512];

    const int t = threadIdx.x;
    const int bh = blockIdx.y;
    const int q0 = blockIdx.x << 7;
    const uint32_t ub = smem_u32(smb);

    if (t < 128) {
        float2 s1 = g_stat1[bh * L_ + q0 + t];
        float2 s2 = g_stat2[bh * L_ + q0 + t];
        sStat[t] = s1.x; sStat[128 + t] = s1.y;
        sStat[256 + t] = s2.x; sStat[384 + t] = s2.y;
    }

    const float* l1base = g_l1 + ((size_t)bh * L_ + q0) * L_;
    float* l2base = attn + ((size_t)bh * L_ + q0) * L_;

    {
        #pragma unroll
        for (int i = 0; i < 8; i++) {
            int lin = t + i * 512;
            int tile = lin >> 11, idx = lin & 2047;
            int row = idx >> 4, pc = idx & 15;
            const float* src = (tile ? l2base : l1base) + (size_t)row * L_ + pc * 4;
            cp16(ub + (tile ? RAW2_(0) : RAW1_(0)) + idx * 16, src);
        }
        #pragma unroll
        for (int i = 0; i < 2; i++) {
            int lin = t + i * 512;
            int tile = lin >> 9, r = (lin >> 3) & 63, pc = lin & 7;
            const __nv_bfloat16* vs =
                (tile ? g_Vtl : g_Vth) + ((size_t)bh * DK_ + r) * L_ + pc * 8;
            cp16(ub + (tile ? VL_(0) : VH_(0)) + r * 144 + pc * 16, vs);
        }
        CP_COMMIT();
    }

    const int w = t >> 5, lane = t & 31;
    const int wm = (w >> 1) << 4;    // 0..112
    const int wn = (w & 1) << 5;     // 0,32
    const int gid = lane >> 2, tig = lane & 3;

    __nv_bfloat16* sAh = (__nv_bfloat16*)(smb + SAH_);
    __nv_bfloat16* sAl = (__nv_bfloat16*)(smb + SAL_);

    float acc[4][4] = {};

    for (int kt = 0; kt < 16; kt++) {
        const int k0 = kt << 6;
        const int cur = kt & 1;
        if (kt < 15) {
            const int nxt = cur ^ 1;
            const int kn = k0 + 64;
            #pragma unroll
            for (int i = 0; i < 8; i++) {
                int lin = t + i * 512;
                int tile = lin >> 11, idx = lin & 2047;
                int row = idx >> 4, pc = idx & 15;
                const float* src = (tile ? l2base : l1base) + (size_t)row * L_ + kn + pc * 4;
                cp16(ub + (tile ? RAW2_(nxt) : RAW1_(nxt)) + idx * 16, src);
            }
            #pragma unroll
            for (int i = 0; i < 2; i++) {
                int lin = t + i * 512;
                int tile = lin >> 9, r = (lin >> 3) & 63, pc = lin & 7;
                const __nv_bfloat16* vs =
                    (tile ? g_Vtl : g_Vth) + ((size_t)bh * DK_ + r) * L_ + kn + pc * 8;
                cp16(ub + (tile ? VL_(nxt) : VH_(nxt)) + r * 144 + pc * 16, vs);
            }
            CP_COMMIT();
            CP_WAIT(1);
        } else {
            CP_WAIT(0);
        }
        __syncthreads();

        const float* r1 = (const float*)(smb + RAW1_(cur));
        const float* r2 = (const float*)(smb + RAW2_(cur));
        #pragma unroll
        for (int i = 0; i < 4; i++) {
            int lin = t + i * 512;
            int row = lin >> 4, pc = lin & 15;
            float4 x1 = *(const float4*)(r1 + lin * 4);
            float4 x2 = *(const float4*)(r2 + lin * 4);
            float M1 = sStat[row], I1 = sStat[128 + row];
            float M2 = sStat[256 + row], I2 = sStat[384 + row];
            float f[4];
            f[0] = __expf(x1.x - M1) * I1 + __expf(x2.x - M2) * I2;
            f[1] = __expf(x1.y - M1) * I1 + __expf(x2.y - M2) * I2;
            f[2] = __expf(x1.z - M1) * I1 + __expf(x2.z - M2) * I2;
            f[3] = __expf(x1.w - M1) * I1 + __expf(x2.w - M2) * I2;
            __stcs((float4*)(l2base + (size_t)row * L_ + k0 + pc * 4),
                   make_float4(f[0], f[1], f[2], f[3]));
            uint2 hp, lp;
            split_pack4(f, hp, lp);
            *(uint2*)(sAh + row * ST + pc * 4) = hp;
            *(uint2*)(sAl + row * ST + pc * 4) = lp;
        }
        __syncthreads();

        const __nv_bfloat16* sVh = (const __nv_bfloat16*)(smb + VH_(cur));
        const __nv_bfloat16* sVl = (const __nv_bfloat16*)(smb + VL_(cur));
        #pragma unroll
        for (int k1 = 0; k1 < 64; k1 += 16) {
            uint32_t ah[4], al[4];
            {
                int r = wm + gid;
                ah[0] = *(const uint32_t*)(sAh + r * ST + k1 + tig * 2);
                ah[1] = *(const uint32_t*)(sAh + (r + 8) * ST + k1 + tig * 2);
                ah[2] = *(const uint32_t*)(sAh + r * ST + k1 + tig * 2 + 8);
                ah[3] = *(const uint32_t*)(sAh + (r + 8) * ST + k1 + tig * 2 + 8);
                al[0] = *(const uint32_t*)(sAl + r * ST + k1 + tig * 2);
                al[1] = *(const uint32_t*)(sAl + (r + 8) * ST + k1 + tig * 2);
                al[2] = *(const uint32_t*)(sAl + r * ST + k1 + tig * 2 + 8);
                al[3] = *(const uint32_t*)(sAl + (r + 8) * ST + k1 + tig * 2 + 8);
            }
            uint32_t bhf[4][2], blf[4][2];
            #pragma unroll
            for (int j = 0; j < 4; j++) {
                int r = wn + j * 8 + gid;
                bhf[j][0] = *(const uint32_t*)(sVh + r * ST + k1 + tig * 2);
                bhf[j][1] = *(const uint32_t*)(sVh + r * ST + k1 + tig * 2 + 8);
                blf[j][0] = *(const uint32_t*)(sVl + r * ST + k1 + tig * 2);
                blf[j][1] = *(const uint32_t*)(sVl + r * ST + k1 + tig * 2 + 8);
            }
            #pragma unroll
            for (int j = 0; j < 4; j++) {
                mma_bf16(acc[j], ah, bhf[j][0], bhf[j][1]);
                mma_bf16(acc[j], ah, blf[j][0], blf[j][1]);
                mma_bf16(acc[j], al, bhf[j][0], bhf[j][1]);
            }
        }
        __syncthreads();
    }

    #pragma unroll
    for (int j = 0; j < 4; j++) {
        int m = q0 + wm + gid;
        int n = wn + j * 8 + tig * 2;
        *(float2*)(ctx + ((size_t)bh * L_ + m) * DK_ + n) =
            make_float2(acc[j][0], acc[j][1]);
        *(float2*)(ctx + ((size_t)bh * L_ + m + 8) * DK_ + n) =
            make_float2(acc[j][2], acc[j][3]);
    }
}

// ---------------------------------------------------------------------------
extern "C" void kernel_launch(void* const* d_in, const int* in_sizes, int n_in,
                              void* d_out, int out_size) {
    const float* Q = (const float*)d_in[0];
    const float* K = (const float*)d_in[1];
    const float* V = (const float*)d_in[2];
    const float* W = (const float*)d_in[3];
    float* ctx  = (float*)d_out;                    // [B,H,L,Dv]
    float* attn = ctx + (size_t)BH_ * L_ * DK_;     // [B,H,L,L]

    // Prep
    cat_kernel<<<BH_ * L_ * 32 / 256, 256>>>(Q, K);
    wsplit_kernel<<<H_ * L_ * 32 / 256, 256>>>(W);
    vtrans_kernel<<<dim3(L_ / 64, BH_), 256>>>(V);

    // n-persistent logits (+ in-kernel row stats), 256 threads, ldmatrix frags
    const int smem0 = 6 * 128 * (64 + 8) * 2;    // 110,592
    const int smem1 = 6 * 128 * (128 + 8) * 2;   // 208,896
    cudaFuncSetAttribute(mm_logits_kernel<0>,
                         cudaFuncAttributeMaxDynamicSharedMemorySize, smem0);
    cudaFuncSetAttribute(mm_logits_kernel<1>,
                         cudaFuncAttributeMaxDynamicSharedMemorySize, smem1);
    mm_logits_kernel<0><<<dim3(8, BH_), 256, smem0>>>(attn);
    mm_logits_kernel<1><<<dim3(8, BH_), 256, smem1>>>(attn);

    // Fused softmax-add + AV (cp.async pipelined)
    cudaFuncSetAttribute(fused_attn_av_kernel,
                         cudaFuncAttributeMaxDynamicSharedMemorySize, SMEMF_);
    fused_attn_av_kernel<<<dim3(8, BH_), 512, SMEMF_>>>(attn, ctx);
}